// round 1
// baseline (speedup 1.0000x reference)
#include <cuda_runtime.h>
#include <math.h>
#include <float.h>

#define NN 50000
#define EE 400000
#define E2T (EE + NN)
#define ND 128
#define ED 64
#define HID 128
#define GIN 258
#define CIN 320

// ---------------- scratch (static device allocations; no cudaMalloc) ----------------
__device__ float g_xsum_out[NN * ND];
__device__ float g_xsum_in [NN * ND];
__device__ int   g_deg_out [NN];
__device__ int   g_deg_in  [NN];
__device__ float g_loop    [NN * ED];     // loop_sum -> loop_attr (in place)
__device__ float g_xi      [NN * GIN];
__device__ float g_xl1     [NN * 256];
__device__ float g_xr1     [NN * 256];
__device__ float g_logit1  [E2T * 2];
__device__ float g_m1      [NN * 2];
__device__ float g_den1    [NN * 2];
__device__ float g_acc1    [NN * 256];
__device__ float g_h1      [NN * HID];
__device__ float g_xl2     [NN * HID];
__device__ float g_xr2     [NN * HID];
__device__ float g_logit2  [E2T];
__device__ float g_m2      [NN];
__device__ float g_den2    [NN];
__device__ float g_acc2    [NN * HID];
__device__ float g_h2      [NN * HID];

// ---------------- helpers ----------------
__device__ __forceinline__ void atomicMaxF(float* addr, float val) {
    int* ia = (int*)addr;
    int old = *ia;
    while (__int_as_float(old) < val) {
        int assumed = old;
        old = atomicCAS(ia, assumed, __float_as_int(val));
        if (old == assumed) break;
    }
}

__global__ void k_fill_neg(float* p, int n) {
    int i = blockIdx.x * blockDim.x + threadIdx.x;
    if (i < n) p[i] = -FLT_MAX;
}

// ---------------- stage 1: degrees + loop_attr sum ----------------
__global__ void k_deg_loop(const int* __restrict__ src, const int* __restrict__ dst,
                           const float* __restrict__ ea,
                           int* __restrict__ deg_out, int* __restrict__ deg_in,
                           float* __restrict__ loop) {
    int tid = blockIdx.x * blockDim.x + threadIdx.x;
    if (tid >= EE * 16) return;
    int e = tid >> 4, q = tid & 15;
    int d = dst[e];
    if (q == 0) {
        atomicAdd(&deg_in[d], 1);
        atomicAdd(&deg_out[src[e]], 1);
    }
    float4 v = ((const float4*)(ea + (size_t)e * ED))[q];
    atomicAdd((float4*)(loop + (size_t)d * ED + q * 4), v);
}

// ---------------- stage 2: emb = relu(ea@epw+epb); scatter to xsum_out[src], xsum_in[dst] ----------------
__global__ void k_embed_scatter(const int* __restrict__ src, const int* __restrict__ dst,
                                const float* __restrict__ ea,
                                const float* __restrict__ epw, const float* __restrict__ epb,
                                float* __restrict__ xsum_out, float* __restrict__ xsum_in) {
    __shared__ float4 wsh[ED * 32];   // [64][128] as float4 [64][32]
    __shared__ float4 bsh4[32];
    __shared__ float  easm[8][ED];
    int tid = threadIdx.x;
    for (int i = tid; i < ED * 32; i += 256) wsh[i] = ((const float4*)epw)[i];
    if (tid < 32) bsh4[tid] = ((const float4*)epb)[tid];
    __syncthreads();
    int sub = tid >> 5;   // edge slot 0..7
    int q   = tid & 31;   // feature quad 0..31
    for (int base = blockIdx.x * 8; base < EE; base += gridDim.x * 8) {
        // load 8 edge_attr rows (512 floats) cooperatively
        #pragma unroll
        for (int r = 0; r < 2; r++) {
            int idx = tid + r * 256;
            int ee = base + (idx >> 6);
            if (ee < EE) easm[idx >> 6][idx & 63] = ea[(size_t)ee * ED + (idx & 63)];
        }
        __syncthreads();
        int e = base + sub;
        if (e < EE) {
            float4 acc = bsh4[q];
            const float* er = easm[sub];
            #pragma unroll
            for (int k = 0; k < ED; k++) {
                float b = er[k];
                float4 w = wsh[k * 32 + q];
                acc.x = fmaf(b, w.x, acc.x); acc.y = fmaf(b, w.y, acc.y);
                acc.z = fmaf(b, w.z, acc.z); acc.w = fmaf(b, w.w, acc.w);
            }
            acc.x = fmaxf(acc.x, 0.f); acc.y = fmaxf(acc.y, 0.f);
            acc.z = fmaxf(acc.z, 0.f); acc.w = fmaxf(acc.w, 0.f);
            int s = src[e], d = dst[e];
            atomicAdd((float4*)(xsum_out + (size_t)s * ND + q * 4), acc);
            atomicAdd((float4*)(xsum_in  + (size_t)d * ND + q * 4), acc);
        }
        __syncthreads();
    }
}

// ---------------- stage 3: build xi, finalize loop_attr ----------------
__global__ void k_build_xi(const float* __restrict__ node_stats,
                           const float* __restrict__ xsum_out, const float* __restrict__ xsum_in,
                           const int* __restrict__ deg_out, const int* __restrict__ deg_in,
                           float* __restrict__ xi) {
    int tid = blockIdx.x * blockDim.x + threadIdx.x;
    if (tid >= NN * GIN) return;
    int i = tid / GIN, j = tid - i * GIN;
    float v;
    if (j < 128)      v = xsum_out[i * 128 + j]        / fmaxf((float)deg_out[i], 1.f);
    else if (j < 256) v = xsum_in [i * 128 + (j - 128)] / fmaxf((float)deg_in [i], 1.f);
    else              v = node_stats[i * 2 + (j - 256)];
    xi[tid] = v;
}

__global__ void k_loop_div(float* __restrict__ loop, const int* __restrict__ deg_in) {
    int tid = blockIdx.x * blockDim.x + threadIdx.x;
    if (tid >= NN * ED) return;
    int i = tid >> 6;
    loop[tid] = loop[tid] / fmaxf((float)deg_in[i], 1.f);
}

// ---------------- generic fp32 tiled GEMM: C[M,Nc] = A[M,K] @ B[K,Nc] (row-major) --------
#define BM 64
#define BN 64
#define BKK 16
__global__ void k_gemm(const float* __restrict__ A, const float* __restrict__ B,
                       float* __restrict__ C, int M, int K, int Nc) {
    __shared__ float As[BKK][BM + 1];
    __shared__ float Bs[BKK][BN + 1];
    int brow = blockIdx.y * BM, bcol = blockIdx.x * BN;
    int tid = threadIdx.x;
    int tr = tid >> 4, tc = tid & 15;
    float acc[4][4] = {};
    for (int k0 = 0; k0 < K; k0 += BKK) {
        for (int i = tid; i < BM * BKK; i += 256) {
            int r = i >> 4, c = i & 15;
            int gr = brow + r, gc = k0 + c;
            As[c][r] = (gr < M && gc < K) ? A[(size_t)gr * K + gc] : 0.f;
        }
        for (int i = tid; i < BKK * BN; i += 256) {
            int r = i >> 6, c = i & 63;
            int gr = k0 + r, gc = bcol + c;
            Bs[r][c] = (gr < K && gc < Nc) ? B[(size_t)gr * Nc + gc] : 0.f;
        }
        __syncthreads();
        #pragma unroll
        for (int kk = 0; kk < BKK; kk++) {
            float a[4], b[4];
            #pragma unroll
            for (int i = 0; i < 4; i++) a[i] = As[kk][tr * 4 + i];
            #pragma unroll
            for (int j = 0; j < 4; j++) b[j] = Bs[kk][tc * 4 + j];
            #pragma unroll
            for (int i = 0; i < 4; i++)
                #pragma unroll
                for (int j = 0; j < 4; j++)
                    acc[i][j] = fmaf(a[i], b[j], acc[i][j]);
        }
        __syncthreads();
    }
    #pragma unroll
    for (int i = 0; i < 4; i++) {
        int row = brow + tr * 4 + i;
        if (row >= M) continue;
        #pragma unroll
        for (int j = 0; j < 4; j++) {
            int col = bcol + tc * 4 + j;
            if (col < Nc) C[(size_t)row * Nc + col] = acc[i][j];
        }
    }
}

// ---------------- GATv2 pass A: logits + segment max ----------------
// OUT = H*128.  blockDim = OUT.  Edge-proj weight column held in registers.
template <int OUT, int H>
__global__ void k_gat_logits(const float* __restrict__ xl, const float* __restrict__ xr,
                             const float* __restrict__ ea, const float* __restrict__ loop,
                             const float* __restrict__ we, const float* __restrict__ att,
                             const int* __restrict__ src, const int* __restrict__ dst,
                             float* __restrict__ logit, float* __restrict__ m) {
    __shared__ float easm[ED];
    __shared__ float part[OUT / 32];
    int t = threadIdx.x;
    float wreg[ED];
    #pragma unroll
    for (int k = 0; k < ED; k++) wreg[k] = we[k * OUT + t];
    float attv = att[t];
    int warp = t >> 5, lane = t & 31;
    for (int e = blockIdx.x; e < E2T; e += gridDim.x) {
        int s, d; const float* row;
        if (e < EE) { s = src[e]; d = dst[e]; row = ea + (size_t)e * ED; }
        else        { s = e - EE; d = s;      row = loop + (size_t)s * ED; }
        if (t < ED) easm[t] = row[t];
        __syncthreads();
        float ew = 0.f;
        #pragma unroll
        for (int k = 0; k < ED; k++) ew = fmaf(easm[k], wreg[k], ew);
        float v = ew + xl[(size_t)s * OUT + t] + xr[(size_t)d * OUT + t];
        v = v > 0.f ? v : 0.2f * v;       // leaky_relu(0.2)
        v *= attv;
        #pragma unroll
        for (int o = 16; o; o >>= 1) v += __shfl_xor_sync(0xffffffffu, v, o);
        if (lane == 0) part[warp] = v;
        __syncthreads();
        if ((t & 127) == 0) {
            float lg = part[warp] + part[warp + 1] + part[warp + 2] + part[warp + 3];
            int h = t >> 7;
            logit[(size_t)e * H + h] = lg;
            atomicMaxF(&m[d * H + h], lg);
        }
        __syncthreads();
    }
}

// ---------------- GATv2 pass B: a = exp(logit - m[d]); denom += a ----------------
template <int H>
__global__ void k_softmax_e(float* __restrict__ logit, const float* __restrict__ m,
                            float* __restrict__ den, const int* __restrict__ dst) {
    int tid = blockIdx.x * blockDim.x + threadIdx.x;
    if (tid >= E2T * H) return;
    int e = tid / H, h = tid - e * H;
    int d = (e < EE) ? dst[e] : (e - EE);
    float mm = m[d * H + h];
    if (mm == -FLT_MAX) mm = 0.f;
    float a = expf(logit[tid] - mm);
    logit[tid] = a;
    atomicAdd(&den[d * H + h], a);
}

// ---------------- GATv2 pass C: acc[d] += xl[s] * a/den ----------------
template <int OUT, int H>
__global__ void k_gat_aggregate(const float* __restrict__ xl, const float* __restrict__ logit,
                                const float* __restrict__ den, const int* __restrict__ src,
                                const int* __restrict__ dst, float* __restrict__ acc) {
    const int Q = OUT / 4;
    int tid = blockIdx.x * blockDim.x + threadIdx.x;
    if (tid >= E2T * Q) return;
    int e = tid / Q, q = tid - e * Q;
    int s, d;
    if (e < EE) { s = src[e]; d = dst[e]; } else { s = d = e - EE; }
    int h = (q * 4) >> 7;
    float a = logit[(size_t)e * H + h];
    float dn = den[d * H + h];
    float coef = a / fmaxf(dn, 1e-16f);
    float4 x = *(const float4*)(xl + (size_t)s * OUT + q * 4);
    x.x *= coef; x.y *= coef; x.z *= coef; x.w *= coef;
    atomicAdd((float4*)(acc + (size_t)d * OUT + q * 4), x);
}

// ---------------- finalize: head-mean + bias, LayerNorm, ELU ----------------
template <int H>
__global__ void k_finalize(const float* __restrict__ acc, const float* __restrict__ bias,
                           const float* __restrict__ g, const float* __restrict__ b,
                           float* __restrict__ out) {
    __shared__ float sb[4];
    int i = blockIdx.x, t = threadIdx.x;
    float v;
    if (H == 2) v = 0.5f * (acc[(size_t)i * 256 + t] + acc[(size_t)i * 256 + 128 + t]) + bias[t];
    else        v = acc[(size_t)i * 128 + t] + bias[t];
    float s = v;
    #pragma unroll
    for (int o = 16; o; o >>= 1) s += __shfl_xor_sync(0xffffffffu, s, o);
    if ((t & 31) == 0) sb[t >> 5] = s;
    __syncthreads();
    float mu = (sb[0] + sb[1] + sb[2] + sb[3]) * (1.f / 128.f);
    __syncthreads();
    float dv = v - mu;
    s = dv * dv;
    #pragma unroll
    for (int o = 16; o; o >>= 1) s += __shfl_xor_sync(0xffffffffu, s, o);
    if ((t & 31) == 0) sb[t >> 5] = s;
    __syncthreads();
    float var = (sb[0] + sb[1] + sb[2] + sb[3]) * (1.f / 128.f);
    float o2 = dv * rsqrtf(var + 1e-5f) * g[t] + b[t];
    out[(size_t)i * 128 + t] = o2 > 0.f ? o2 : (expf(o2) - 1.f);
}

// ---------------- classifier: per-edge 320->128->64->1 MLP, warp per edge ----------------
#define CLS_NW 8
#define CLS_SMEM_FLOATS (CIN*HID + HID*64 + 64 + 128 + 64 + CLS_NW*CIN + CLS_NW*HID)
__global__ void __launch_bounds__(256, 1)
k_classifier(const float* __restrict__ h2, const float* __restrict__ ea,
             const int* __restrict__ src, const int* __restrict__ dst,
             const float* __restrict__ c1w, const float* __restrict__ c1b,
             const float* __restrict__ c2w, const float* __restrict__ c2b,
             const float* __restrict__ c3w, const float* __restrict__ c3b,
             float* __restrict__ out) {
    extern __shared__ float sm[];
    float* c1s = sm;                       // 40960
    float* c2s = c1s + CIN * HID;          // 8192
    float* c3s = c2s + HID * 64;           // 64
    float* b1s = c3s + 64;                 // 128
    float* b2s = b1s + 128;                // 64
    float* ers = b2s + 64;                 // NW*320
    float* hbs = ers + CLS_NW * CIN;       // NW*128
    int tid = threadIdx.x;
    for (int i = tid; i < CIN * HID; i += 256) c1s[i] = c1w[i];
    for (int i = tid; i < HID * 64; i += 256) c2s[i] = c2w[i];
    if (tid < 64)  c3s[tid] = c3w[tid];
    if (tid < 128) b1s[tid] = c1b[tid];
    if (tid < 64)  b2s[tid] = c2b[tid];
    __syncthreads();
    float c3bv = c3b[0];
    int warp = tid >> 5, lane = tid & 31;
    float* er = ers + warp * CIN;
    float* hb = hbs + warp * HID;
    int nwarps = gridDim.x * CLS_NW;
    for (int e = blockIdx.x * CLS_NW + warp; e < EE; e += nwarps) {
        int s = src[e], d = dst[e];
        #pragma unroll
        for (int r = 0; r < 4; r++) er[lane + r * 32]       = h2[(size_t)s * HID + lane + r * 32];
        #pragma unroll
        for (int r = 0; r < 4; r++) er[128 + lane + r * 32] = h2[(size_t)d * HID + lane + r * 32];
        #pragma unroll
        for (int r = 0; r < 2; r++) er[256 + lane + r * 32] = ea[(size_t)e * ED + lane + r * 32];
        __syncwarp();
        float4 a1 = ((float4*)b1s)[lane];
        #pragma unroll 4
        for (int k = 0; k < CIN; k++) {
            float bb = er[k];
            float4 w = ((float4*)c1s)[k * 32 + lane];
            a1.x = fmaf(bb, w.x, a1.x); a1.y = fmaf(bb, w.y, a1.y);
            a1.z = fmaf(bb, w.z, a1.z); a1.w = fmaf(bb, w.w, a1.w);
        }
        a1.x = fmaxf(a1.x, 0.f); a1.y = fmaxf(a1.y, 0.f);
        a1.z = fmaxf(a1.z, 0.f); a1.w = fmaxf(a1.w, 0.f);
        ((float4*)hb)[lane] = a1;
        __syncwarp();
        float2 a2 = ((float2*)b2s)[lane];
        #pragma unroll 4
        for (int k = 0; k < HID; k++) {
            float bb = hb[k];
            float2 w = ((float2*)c2s)[k * 32 + lane];
            a2.x = fmaf(bb, w.x, a2.x); a2.y = fmaf(bb, w.y, a2.y);
        }
        a2.x = fmaxf(a2.x, 0.f); a2.y = fmaxf(a2.y, 0.f);
        float v = a2.x * c3s[lane * 2] + a2.y * c3s[lane * 2 + 1];
        #pragma unroll
        for (int o = 16; o; o >>= 1) v += __shfl_xor_sync(0xffffffffu, v, o);
        if (lane == 0) out[e] = v + c3bv;
        __syncwarp();
    }
}

// ---------------- launch ----------------
static inline int cdiv(long a, long b) { return (int)((a + b - 1) / b); }

extern "C" void kernel_launch(void* const* d_in, const int* in_sizes, int n_in,
                              void* d_out, int out_size) {
    const float* node_stats = (const float*)d_in[1];
    const int*   ei   = (const int*)d_in[2];
    const int*   src  = ei;
    const int*   dst  = ei + EE;
    const float* ea   = (const float*)d_in[3];
    const float* epw  = (const float*)d_in[4];
    const float* epb  = (const float*)d_in[5];
    const float* g1wl = (const float*)d_in[6];
    const float* g1wr = (const float*)d_in[7];
    const float* g1we = (const float*)d_in[8];
    const float* g1att= (const float*)d_in[9];
    const float* g1b  = (const float*)d_in[10];
    const float* n1g  = (const float*)d_in[11];
    const float* n1b  = (const float*)d_in[12];
    const float* g2wl = (const float*)d_in[13];
    const float* g2wr = (const float*)d_in[14];
    const float* g2we = (const float*)d_in[15];
    const float* g2att= (const float*)d_in[16];
    const float* g2b  = (const float*)d_in[17];
    const float* n2g  = (const float*)d_in[18];
    const float* n2b  = (const float*)d_in[19];
    const float* c1w  = (const float*)d_in[20];
    const float* c1b  = (const float*)d_in[21];
    const float* c2w  = (const float*)d_in[22];
    const float* c2b  = (const float*)d_in[23];
    const float* c3w  = (const float*)d_in[24];
    const float* c3b  = (const float*)d_in[25];
    float* out = (float*)d_out;

    float *xsum_out, *xsum_in, *loop, *xi, *xl1, *xr1, *logit1, *m1, *den1, *acc1, *h1;
    float *xl2, *xr2, *logit2, *m2, *den2, *acc2, *h2;
    int *deg_out, *deg_in;
    cudaGetSymbolAddress((void**)&xsum_out, g_xsum_out);
    cudaGetSymbolAddress((void**)&xsum_in,  g_xsum_in);
    cudaGetSymbolAddress((void**)&deg_out,  g_deg_out);
    cudaGetSymbolAddress((void**)&deg_in,   g_deg_in);
    cudaGetSymbolAddress((void**)&loop,     g_loop);
    cudaGetSymbolAddress((void**)&xi,       g_xi);
    cudaGetSymbolAddress((void**)&xl1,      g_xl1);
    cudaGetSymbolAddress((void**)&xr1,      g_xr1);
    cudaGetSymbolAddress((void**)&logit1,   g_logit1);
    cudaGetSymbolAddress((void**)&m1,       g_m1);
    cudaGetSymbolAddress((void**)&den1,     g_den1);
    cudaGetSymbolAddress((void**)&acc1,     g_acc1);
    cudaGetSymbolAddress((void**)&h1,       g_h1);
    cudaGetSymbolAddress((void**)&xl2,      g_xl2);
    cudaGetSymbolAddress((void**)&xr2,      g_xr2);
    cudaGetSymbolAddress((void**)&logit2,   g_logit2);
    cudaGetSymbolAddress((void**)&m2,       g_m2);
    cudaGetSymbolAddress((void**)&den2,     g_den2);
    cudaGetSymbolAddress((void**)&acc2,     g_acc2);
    cudaGetSymbolAddress((void**)&h2,       g_h2);

    // init
    cudaMemsetAsync(xsum_out, 0, sizeof(float) * NN * ND);
    cudaMemsetAsync(xsum_in,  0, sizeof(float) * NN * ND);
    cudaMemsetAsync(deg_out,  0, sizeof(int) * NN);
    cudaMemsetAsync(deg_in,   0, sizeof(int) * NN);
    cudaMemsetAsync(loop,     0, sizeof(float) * NN * ED);
    cudaMemsetAsync(den1,     0, sizeof(float) * NN * 2);
    cudaMemsetAsync(den2,     0, sizeof(float) * NN);
    cudaMemsetAsync(acc1,     0, sizeof(float) * NN * 256);
    cudaMemsetAsync(acc2,     0, sizeof(float) * NN * 128);
    k_fill_neg<<<cdiv(NN * 2, 256), 256>>>(m1, NN * 2);
    k_fill_neg<<<cdiv(NN, 256), 256>>>(m2, NN);

    // stage 1+2: degrees, loop sums, embed+scatter
    k_deg_loop<<<cdiv((long)EE * 16, 256), 256>>>(src, dst, ea, deg_out, deg_in, loop);
    k_embed_scatter<<<2048, 256>>>(src, dst, ea, epw, epb, xsum_out, xsum_in);
    k_build_xi<<<cdiv((long)NN * GIN, 256), 256>>>(node_stats, xsum_out, xsum_in, deg_out, deg_in, xi);
    k_loop_div<<<cdiv((long)NN * ED, 256), 256>>>(loop, deg_in);

    // GAT layer 1
    k_gemm<<<dim3(4, cdiv(NN, BM)), 256>>>(xi, g1wl, xl1, NN, GIN, 256);
    k_gemm<<<dim3(4, cdiv(NN, BM)), 256>>>(xi, g1wr, xr1, NN, GIN, 256);
    k_gat_logits<256, 2><<<2048, 256>>>(xl1, xr1, ea, loop, g1we, g1att, src, dst, logit1, m1);
    k_softmax_e<2><<<cdiv((long)E2T * 2, 256), 256>>>(logit1, m1, den1, dst);
    k_gat_aggregate<256, 2><<<cdiv((long)E2T * 64, 256), 256>>>(xl1, logit1, den1, src, dst, acc1);
    k_finalize<2><<<NN, 128>>>(acc1, g1b, n1g, n1b, h1);

    // GAT layer 2
    k_gemm<<<dim3(2, cdiv(NN, BM)), 256>>>(h1, g2wl, xl2, NN, HID, HID);
    k_gemm<<<dim3(2, cdiv(NN, BM)), 256>>>(h1, g2wr, xr2, NN, HID, HID);
    k_gat_logits<128, 1><<<2048, 128>>>(xl2, xr2, ea, loop, g2we, g2att, src, dst, logit2, m2);
    k_softmax_e<1><<<cdiv((long)E2T, 256), 256>>>(logit2, m2, den2, dst);
    k_gat_aggregate<128, 1><<<cdiv((long)E2T * 32, 256), 256>>>(xl2, logit2, den2, src, dst, acc2);
    k_finalize<1><<<NN, 128>>>(acc2, g2b, n2g, n2b, h2);

    // classifier
    cudaFuncSetAttribute(k_classifier, cudaFuncAttributeMaxDynamicSharedMemorySize,
                         CLS_SMEM_FLOATS * sizeof(float));
    k_classifier<<<296, 256, CLS_SMEM_FLOATS * sizeof(float)>>>(
        h2, ea, src, dst, c1w, c1b, c2w, c2b, c3w, c3b, out);
}

// round 2
// speedup vs baseline: 1.1823x; 1.1823x over previous
#include <cuda_runtime.h>
#include <math.h>
#include <float.h>

#define NN 50000
#define EE 400000
#define E2T (EE + NN)
#define ND 128
#define ED 64
#define HID 128
#define GIN 258
#define CIN 320

// ---------------- scratch (static device allocations; no cudaMalloc) ----------------
__device__ float g_xsum_out[NN * ND];
__device__ float g_xsum_in [NN * ND];
__device__ int   g_deg_out [NN];
__device__ int   g_deg_in  [NN];
__device__ float g_loop    [NN * ED];     // loop_sum -> loop_attr (in place)
__device__ float g_xi      [NN * GIN];
__device__ float g_xl1     [NN * 256];
__device__ float g_xr1     [NN * 256];
__device__ float g_logit1  [E2T * 2];
__device__ float g_m1      [NN * 2];
__device__ float g_den1    [NN * 2];
__device__ float g_acc1    [NN * 256];
__device__ float g_h1      [NN * HID];
__device__ float g_xl2     [NN * HID];
__device__ float g_xr2     [NN * HID];
__device__ float g_logit2  [E2T];
__device__ float g_m2      [NN];
__device__ float g_den2    [NN];
__device__ float g_acc2    [NN * HID];
__device__ float g_h2      [NN * HID];

// ---------------- helpers ----------------
__device__ __forceinline__ void atomicMaxF(float* addr, float val) {
    int* ia = (int*)addr;
    int old = *ia;
    while (__int_as_float(old) < val) {
        int assumed = old;
        old = atomicCAS(ia, assumed, __float_as_int(val));
        if (old == assumed) break;
    }
}

__global__ void k_fill_neg(float* p, int n) {
    int i = blockIdx.x * blockDim.x + threadIdx.x;
    if (i < n) p[i] = -FLT_MAX;
}

// ---------------- stage 1+2 fused: embed + scatter + degrees + loop sums ----------------
// 16 edges per block-iteration; each compute thread handles 2 edges so one
// weight LDS.128 feeds 8 FMAs instead of 4.
__global__ void k_embed_scatter(const int* __restrict__ src, const int* __restrict__ dst,
                                const float* __restrict__ ea,
                                const float* __restrict__ epw, const float* __restrict__ epb,
                                float* __restrict__ xsum_out, float* __restrict__ xsum_in,
                                int* __restrict__ deg_out, int* __restrict__ deg_in,
                                float* __restrict__ loop) {
    __shared__ float4 wsh[ED * 32];   // [64][128] as float4 [64][32]
    __shared__ float4 bsh4[32];
    __shared__ float  easm[16][ED];
    int tid = threadIdx.x;
    for (int i = tid; i < ED * 32; i += 256) wsh[i] = ((const float4*)epw)[i];
    if (tid < 32) bsh4[tid] = ((const float4*)epb)[tid];
    __syncthreads();
    int sub = tid >> 5;   // edge slot 0..7 (handles sub and sub+8)
    int q   = tid & 31;   // feature quad 0..31
    for (int base = blockIdx.x * 16; base < EE; base += gridDim.x * 16) {
        // load 16 edge_attr rows (1024 floats) cooperatively
        #pragma unroll
        for (int r = 0; r < 4; r++) {
            int idx = tid + r * 256;
            int ee = base + (idx >> 6);
            if (ee < EE) easm[idx >> 6][idx & 63] = ea[(size_t)ee * ED + (idx & 63)];
        }
        __syncthreads();
        // fused deg + loop-attr accumulation (one float4 atomic per thread)
        {
            int e_loc = tid >> 4, q2 = tid & 15;
            int e = base + e_loc;
            if (e < EE) {
                int d = dst[e];
                if (q2 == 0) {
                    atomicAdd(&deg_in[d], 1);
                    atomicAdd(&deg_out[src[e]], 1);
                }
                float4 v = ((const float4*)easm[e_loc])[q2];
                atomicAdd((float4*)(loop + (size_t)d * ED + q2 * 4), v);
            }
        }
        int e0 = base + sub, e1 = base + sub + 8;
        float4 acc0 = bsh4[q], acc1 = bsh4[q];
        const float* er0 = easm[sub];
        const float* er1 = easm[sub + 8];
        #pragma unroll
        for (int k = 0; k < ED; k++) {
            float4 w = wsh[k * 32 + q];
            float b0 = er0[k], b1 = er1[k];
            acc0.x = fmaf(b0, w.x, acc0.x); acc0.y = fmaf(b0, w.y, acc0.y);
            acc0.z = fmaf(b0, w.z, acc0.z); acc0.w = fmaf(b0, w.w, acc0.w);
            acc1.x = fmaf(b1, w.x, acc1.x); acc1.y = fmaf(b1, w.y, acc1.y);
            acc1.z = fmaf(b1, w.z, acc1.z); acc1.w = fmaf(b1, w.w, acc1.w);
        }
        if (e0 < EE) {
            acc0.x = fmaxf(acc0.x, 0.f); acc0.y = fmaxf(acc0.y, 0.f);
            acc0.z = fmaxf(acc0.z, 0.f); acc0.w = fmaxf(acc0.w, 0.f);
            int s = src[e0], d = dst[e0];
            atomicAdd((float4*)(xsum_out + (size_t)s * ND + q * 4), acc0);
            atomicAdd((float4*)(xsum_in  + (size_t)d * ND + q * 4), acc0);
        }
        if (e1 < EE) {
            acc1.x = fmaxf(acc1.x, 0.f); acc1.y = fmaxf(acc1.y, 0.f);
            acc1.z = fmaxf(acc1.z, 0.f); acc1.w = fmaxf(acc1.w, 0.f);
            int s = src[e1], d = dst[e1];
            atomicAdd((float4*)(xsum_out + (size_t)s * ND + q * 4), acc1);
            atomicAdd((float4*)(xsum_in  + (size_t)d * ND + q * 4), acc1);
        }
        __syncthreads();
    }
}

// ---------------- stage 3: build xi, finalize loop_attr ----------------
__global__ void k_build_xi(const float* __restrict__ node_stats,
                           const float* __restrict__ xsum_out, const float* __restrict__ xsum_in,
                           const int* __restrict__ deg_out, const int* __restrict__ deg_in,
                           float* __restrict__ xi) {
    int tid = blockIdx.x * blockDim.x + threadIdx.x;
    if (tid >= NN * GIN) return;
    int i = tid / GIN, j = tid - i * GIN;
    float v;
    if (j < 128)      v = xsum_out[i * 128 + j]        / fmaxf((float)deg_out[i], 1.f);
    else if (j < 256) v = xsum_in [i * 128 + (j - 128)] / fmaxf((float)deg_in [i], 1.f);
    else              v = node_stats[i * 2 + (j - 256)];
    xi[tid] = v;
}

__global__ void k_loop_div(float* __restrict__ loop, const int* __restrict__ deg_in) {
    int tid = blockIdx.x * blockDim.x + threadIdx.x;
    if (tid >= NN * ED) return;
    int i = tid >> 6;
    loop[tid] = loop[tid] / fmaxf((float)deg_in[i], 1.f);
}

// ---------------- generic fp32 tiled GEMM: C[M,Nc] = A[M,K] @ B[K,Nc] (row-major) --------
#define BM 64
#define BN 64
#define BKK 16
__global__ void k_gemm(const float* __restrict__ A, const float* __restrict__ B,
                       float* __restrict__ C, int M, int K, int Nc) {
    __shared__ float As[BKK][BM + 1];
    __shared__ float Bs[BKK][BN + 1];
    int brow = blockIdx.y * BM, bcol = blockIdx.x * BN;
    int tid = threadIdx.x;
    int tr = tid >> 4, tc = tid & 15;
    float acc[4][4] = {};
    for (int k0 = 0; k0 < K; k0 += BKK) {
        for (int i = tid; i < BM * BKK; i += 256) {
            int r = i >> 4, c = i & 15;
            int gr = brow + r, gc = k0 + c;
            As[c][r] = (gr < M && gc < K) ? A[(size_t)gr * K + gc] : 0.f;
        }
        for (int i = tid; i < BKK * BN; i += 256) {
            int r = i >> 6, c = i & 63;
            int gr = k0 + r, gc = bcol + c;
            Bs[r][c] = (gr < K && gc < Nc) ? B[(size_t)gr * Nc + gc] : 0.f;
        }
        __syncthreads();
        #pragma unroll
        for (int kk = 0; kk < BKK; kk++) {
            float a[4], b[4];
            #pragma unroll
            for (int i = 0; i < 4; i++) a[i] = As[kk][tr * 4 + i];
            #pragma unroll
            for (int j = 0; j < 4; j++) b[j] = Bs[kk][tc * 4 + j];
            #pragma unroll
            for (int i = 0; i < 4; i++)
                #pragma unroll
                for (int j = 0; j < 4; j++)
                    acc[i][j] = fmaf(a[i], b[j], acc[i][j]);
        }
        __syncthreads();
    }
    #pragma unroll
    for (int i = 0; i < 4; i++) {
        int row = brow + tr * 4 + i;
        if (row >= M) continue;
        #pragma unroll
        for (int j = 0; j < 4; j++) {
            int col = bcol + tc * 4 + j;
            if (col < Nc) C[(size_t)row * Nc + col] = acc[i][j];
        }
    }
}

// ---------------- GATv2 pass A: logits + segment max ----------------
template <int OUT, int H>
__global__ void k_gat_logits(const float* __restrict__ xl, const float* __restrict__ xr,
                             const float* __restrict__ ea, const float* __restrict__ loop,
                             const float* __restrict__ we, const float* __restrict__ att,
                             const int* __restrict__ src, const int* __restrict__ dst,
                             float* __restrict__ logit, float* __restrict__ m) {
    __shared__ float easm[ED];
    __shared__ float part[OUT / 32];
    int t = threadIdx.x;
    float wreg[ED];
    #pragma unroll
    for (int k = 0; k < ED; k++) wreg[k] = we[k * OUT + t];
    float attv = att[t];
    int warp = t >> 5, lane = t & 31;
    for (int e = blockIdx.x; e < E2T; e += gridDim.x) {
        int s, d; const float* row;
        if (e < EE) { s = src[e]; d = dst[e]; row = ea + (size_t)e * ED; }
        else        { s = e - EE; d = s;      row = loop + (size_t)s * ED; }
        if (t < ED) easm[t] = row[t];
        __syncthreads();
        float ew = 0.f;
        #pragma unroll
        for (int k = 0; k < ED; k++) ew = fmaf(easm[k], wreg[k], ew);
        float v = ew + xl[(size_t)s * OUT + t] + xr[(size_t)d * OUT + t];
        v = v > 0.f ? v : 0.2f * v;       // leaky_relu(0.2)
        v *= attv;
        #pragma unroll
        for (int o = 16; o; o >>= 1) v += __shfl_xor_sync(0xffffffffu, v, o);
        if (lane == 0) part[warp] = v;
        __syncthreads();
        if ((t & 127) == 0) {
            float lg = part[warp] + part[warp + 1] + part[warp + 2] + part[warp + 3];
            int h = t >> 7;
            logit[(size_t)e * H + h] = lg;
            atomicMaxF(&m[d * H + h], lg);
        }
        __syncthreads();
    }
}

// ---------------- GATv2 pass B: a = exp(logit - m[d]); denom += a ----------------
template <int H>
__global__ void k_softmax_e(float* __restrict__ logit, const float* __restrict__ m,
                            float* __restrict__ den, const int* __restrict__ dst) {
    int tid = blockIdx.x * blockDim.x + threadIdx.x;
    if (tid >= E2T * H) return;
    int e = tid / H, h = tid - e * H;
    int d = (e < EE) ? dst[e] : (e - EE);
    float mm = m[d * H + h];
    if (mm == -FLT_MAX) mm = 0.f;
    float a = expf(logit[tid] - mm);
    logit[tid] = a;
    atomicAdd(&den[d * H + h], a);
}

// ---------------- GATv2 pass C: acc[d] += xl[s] * a/den ----------------
template <int OUT, int H>
__global__ void k_gat_aggregate(const float* __restrict__ xl, const float* __restrict__ logit,
                                const float* __restrict__ den, const int* __restrict__ src,
                                const int* __restrict__ dst, float* __restrict__ acc) {
    const int Q = OUT / 4;
    int tid = blockIdx.x * blockDim.x + threadIdx.x;
    if (tid >= E2T * Q) return;
    int e = tid / Q, q = tid - e * Q;
    int s, d;
    if (e < EE) { s = src[e]; d = dst[e]; } else { s = d = e - EE; }
    int h = (q * 4) >> 7;
    float a = logit[(size_t)e * H + h];
    float dn = den[d * H + h];
    float coef = a / fmaxf(dn, 1e-16f);
    float4 x = *(const float4*)(xl + (size_t)s * OUT + q * 4);
    x.x *= coef; x.y *= coef; x.z *= coef; x.w *= coef;
    atomicAdd((float4*)(acc + (size_t)d * OUT + q * 4), x);
}

// ---------------- finalize: head-mean + bias, LayerNorm, ELU ----------------
template <int H>
__global__ void k_finalize(const float* __restrict__ acc, const float* __restrict__ bias,
                           const float* __restrict__ g, const float* __restrict__ b,
                           float* __restrict__ out) {
    __shared__ float sb[4];
    int i = blockIdx.x, t = threadIdx.x;
    float v;
    if (H == 2) v = 0.5f * (acc[(size_t)i * 256 + t] + acc[(size_t)i * 256 + 128 + t]) + bias[t];
    else        v = acc[(size_t)i * 128 + t] + bias[t];
    float s = v;
    #pragma unroll
    for (int o = 16; o; o >>= 1) s += __shfl_xor_sync(0xffffffffu, s, o);
    if ((t & 31) == 0) sb[t >> 5] = s;
    __syncthreads();
    float mu = (sb[0] + sb[1] + sb[2] + sb[3]) * (1.f / 128.f);
    __syncthreads();
    float dv = v - mu;
    s = dv * dv;
    #pragma unroll
    for (int o = 16; o; o >>= 1) s += __shfl_xor_sync(0xffffffffu, s, o);
    if ((t & 31) == 0) sb[t >> 5] = s;
    __syncthreads();
    float var = (sb[0] + sb[1] + sb[2] + sb[3]) * (1.f / 128.f);
    float o2 = dv * rsqrtf(var + 1e-5f) * g[t] + b[t];
    out[(size_t)i * 128 + t] = o2 > 0.f ? o2 : (expf(o2) - 1.f);
}

// ---------------- classifier: per-edge 320->128->64->1 MLP ----------------
// EB edges per warp; edge rows + hidden held in REGISTERS (shfl broadcast),
// so each weight LDS.128 feeds EB*4 FMAs and total smem stays at weights only.
#define CLS_EB 4
#define CLS_SMEM_FLOATS (CIN*HID + HID*64 + 64 + 128 + 64)
__global__ void __launch_bounds__(256, 1)
k_classifier(const float* __restrict__ h2, const float* __restrict__ ea,
             const int* __restrict__ src, const int* __restrict__ dst,
             const float* __restrict__ c1w, const float* __restrict__ c1b,
             const float* __restrict__ c2w, const float* __restrict__ c2b,
             const float* __restrict__ c3w, const float* __restrict__ c3b,
             float* __restrict__ out) {
    extern __shared__ float sm[];
    float* c1s = sm;                       // 40960
    float* c2s = c1s + CIN * HID;          // 8192
    float* c3s = c2s + HID * 64;           // 64
    float* b1s = c3s + 64;                 // 128
    float* b2s = b1s + 128;                // 64
    int tid = threadIdx.x;
    for (int i = tid; i < CIN * HID; i += 256) c1s[i] = c1w[i];
    for (int i = tid; i < HID * 64; i += 256) c2s[i] = c2w[i];
    if (tid < 64)  c3s[tid] = c3w[tid];
    if (tid < 128) b1s[tid] = c1b[tid];
    if (tid < 64)  b2s[tid] = c2b[tid];
    __syncthreads();
    float c3bv = c3b[0];
    int warp = tid >> 5, lane = tid & 31;
    const int stride = gridDim.x * 8 * CLS_EB;
    for (int e0 = (blockIdx.x * 8 + warp) * CLS_EB; e0 < EE; e0 += stride) {
        // gather edge rows into registers: er[ei][r] = feature (r*32 + lane)
        float er[CLS_EB][10];
        #pragma unroll
        for (int ei = 0; ei < CLS_EB; ei++) {
            int e = e0 + ei;
            if (e < EE) {
                int s = src[e], d = dst[e];
                #pragma unroll
                for (int r = 0; r < 4; r++) er[ei][r]     = h2[(size_t)s * HID + r * 32 + lane];
                #pragma unroll
                for (int r = 0; r < 4; r++) er[ei][4 + r] = h2[(size_t)d * HID + r * 32 + lane];
                er[ei][8] = ea[(size_t)e * ED + lane];
                er[ei][9] = ea[(size_t)e * ED + 32 + lane];
            } else {
                #pragma unroll
                for (int r = 0; r < 10; r++) er[ei][r] = 0.f;
            }
        }
        // layer 1: [EB,320] @ [320,128]; lane owns output cols 4*lane..4*lane+3
        float a1[CLS_EB][4];
        #pragma unroll
        for (int ei = 0; ei < CLS_EB; ei++) {
            float4 bb = ((const float4*)b1s)[lane];
            a1[ei][0] = bb.x; a1[ei][1] = bb.y; a1[ei][2] = bb.z; a1[ei][3] = bb.w;
        }
        #pragma unroll
        for (int r = 0; r < 10; r++) {
            #pragma unroll
            for (int kk = 0; kk < 32; kk++) {
                float4 w = ((const float4*)c1s)[(r * 32 + kk) * 32 + lane];
                #pragma unroll
                for (int ei = 0; ei < CLS_EB; ei++) {
                    float bb = __shfl_sync(0xffffffffu, er[ei][r], kk);
                    a1[ei][0] = fmaf(bb, w.x, a1[ei][0]);
                    a1[ei][1] = fmaf(bb, w.y, a1[ei][1]);
                    a1[ei][2] = fmaf(bb, w.z, a1[ei][2]);
                    a1[ei][3] = fmaf(bb, w.w, a1[ei][3]);
                }
            }
        }
        #pragma unroll
        for (int ei = 0; ei < CLS_EB; ei++)
            #pragma unroll
            for (int c = 0; c < 4; c++) a1[ei][c] = fmaxf(a1[ei][c], 0.f);
        // layer 2: [EB,128] @ [128,64]; hidden feature k lives at lane k>>2, comp k&3
        float a2[CLS_EB][2];
        #pragma unroll
        for (int ei = 0; ei < CLS_EB; ei++) {
            float2 bb = ((const float2*)b2s)[lane];
            a2[ei][0] = bb.x; a2[ei][1] = bb.y;
        }
        #pragma unroll
        for (int kq = 0; kq < 32; kq++) {
            #pragma unroll
            for (int c = 0; c < 4; c++) {
                float2 w = ((const float2*)c2s)[(kq * 4 + c) * 32 + lane];
                #pragma unroll
                for (int ei = 0; ei < CLS_EB; ei++) {
                    float bb = __shfl_sync(0xffffffffu, a1[ei][c], kq);
                    a2[ei][0] = fmaf(bb, w.x, a2[ei][0]);
                    a2[ei][1] = fmaf(bb, w.y, a2[ei][1]);
                }
            }
        }
        // layer 3: dot with c3 (lane owns cols 2*lane, 2*lane+1), warp-reduce
        float w3a = c3s[lane * 2], w3b = c3s[lane * 2 + 1];
        #pragma unroll
        for (int ei = 0; ei < CLS_EB; ei++) {
            float v = fmaxf(a2[ei][0], 0.f) * w3a + fmaxf(a2[ei][1], 0.f) * w3b;
            #pragma unroll
            for (int o = 16; o; o >>= 1) v += __shfl_xor_sync(0xffffffffu, v, o);
            int e = e0 + ei;
            if (lane == 0 && e < EE) out[e] = v + c3bv;
        }
    }
}

// ---------------- launch ----------------
static inline int cdiv(long a, long b) { return (int)((a + b - 1) / b); }

extern "C" void kernel_launch(void* const* d_in, const int* in_sizes, int n_in,
                              void* d_out, int out_size) {
    const float* node_stats = (const float*)d_in[1];
    const int*   ei   = (const int*)d_in[2];
    const int*   src  = ei;
    const int*   dst  = ei + EE;
    const float* ea   = (const float*)d_in[3];
    const float* epw  = (const float*)d_in[4];
    const float* epb  = (const float*)d_in[5];
    const float* g1wl = (const float*)d_in[6];
    const float* g1wr = (const float*)d_in[7];
    const float* g1we = (const float*)d_in[8];
    const float* g1att= (const float*)d_in[9];
    const float* g1b  = (const float*)d_in[10];
    const float* n1g  = (const float*)d_in[11];
    const float* n1b  = (const float*)d_in[12];
    const float* g2wl = (const float*)d_in[13];
    const float* g2wr = (const float*)d_in[14];
    const float* g2we = (const float*)d_in[15];
    const float* g2att= (const float*)d_in[16];
    const float* g2b  = (const float*)d_in[17];
    const float* n2g  = (const float*)d_in[18];
    const float* n2b  = (const float*)d_in[19];
    const float* c1w  = (const float*)d_in[20];
    const float* c1b  = (const float*)d_in[21];
    const float* c2w  = (const float*)d_in[22];
    const float* c2b  = (const float*)d_in[23];
    const float* c3w  = (const float*)d_in[24];
    const float* c3b  = (const float*)d_in[25];
    float* out = (float*)d_out;

    float *xsum_out, *xsum_in, *loop, *xi, *xl1, *xr1, *logit1, *m1, *den1, *acc1, *h1;
    float *xl2, *xr2, *logit2, *m2, *den2, *acc2, *h2;
    int *deg_out, *deg_in;
    cudaGetSymbolAddress((void**)&xsum_out, g_xsum_out);
    cudaGetSymbolAddress((void**)&xsum_in,  g_xsum_in);
    cudaGetSymbolAddress((void**)&deg_out,  g_deg_out);
    cudaGetSymbolAddress((void**)&deg_in,   g_deg_in);
    cudaGetSymbolAddress((void**)&loop,     g_loop);
    cudaGetSymbolAddress((void**)&xi,       g_xi);
    cudaGetSymbolAddress((void**)&xl1,      g_xl1);
    cudaGetSymbolAddress((void**)&xr1,      g_xr1);
    cudaGetSymbolAddress((void**)&logit1,   g_logit1);
    cudaGetSymbolAddress((void**)&m1,       g_m1);
    cudaGetSymbolAddress((void**)&den1,     g_den1);
    cudaGetSymbolAddress((void**)&acc1,     g_acc1);
    cudaGetSymbolAddress((void**)&h1,       g_h1);
    cudaGetSymbolAddress((void**)&xl2,      g_xl2);
    cudaGetSymbolAddress((void**)&xr2,      g_xr2);
    cudaGetSymbolAddress((void**)&logit2,   g_logit2);
    cudaGetSymbolAddress((void**)&m2,       g_m2);
    cudaGetSymbolAddress((void**)&den2,     g_den2);
    cudaGetSymbolAddress((void**)&acc2,     g_acc2);
    cudaGetSymbolAddress((void**)&h2,       g_h2);

    // init
    cudaMemsetAsync(xsum_out, 0, sizeof(float) * NN * ND);
    cudaMemsetAsync(xsum_in,  0, sizeof(float) * NN * ND);
    cudaMemsetAsync(deg_out,  0, sizeof(int) * NN);
    cudaMemsetAsync(deg_in,   0, sizeof(int) * NN);
    cudaMemsetAsync(loop,     0, sizeof(float) * NN * ED);
    cudaMemsetAsync(den1,     0, sizeof(float) * NN * 2);
    cudaMemsetAsync(den2,     0, sizeof(float) * NN);
    cudaMemsetAsync(acc1,     0, sizeof(float) * NN * 256);
    cudaMemsetAsync(acc2,     0, sizeof(float) * NN * 128);
    k_fill_neg<<<cdiv(NN * 2, 256), 256>>>(m1, NN * 2);
    k_fill_neg<<<cdiv(NN, 256), 256>>>(m2, NN);

    // stage 1+2 fused: embed+scatter+degrees+loop
    k_embed_scatter<<<2048, 256>>>(src, dst, ea, epw, epb, xsum_out, xsum_in,
                                   deg_out, deg_in, loop);
    k_build_xi<<<cdiv((long)NN * GIN, 256), 256>>>(node_stats, xsum_out, xsum_in, deg_out, deg_in, xi);
    k_loop_div<<<cdiv((long)NN * ED, 256), 256>>>(loop, deg_in);

    // GAT layer 1
    k_gemm<<<dim3(4, cdiv(NN, BM)), 256>>>(xi, g1wl, xl1, NN, GIN, 256);
    k_gemm<<<dim3(4, cdiv(NN, BM)), 256>>>(xi, g1wr, xr1, NN, GIN, 256);
    k_gat_logits<256, 2><<<2048, 256>>>(xl1, xr1, ea, loop, g1we, g1att, src, dst, logit1, m1);
    k_softmax_e<2><<<cdiv((long)E2T * 2, 256), 256>>>(logit1, m1, den1, dst);
    k_gat_aggregate<256, 2><<<cdiv((long)E2T * 64, 256), 256>>>(xl1, logit1, den1, src, dst, acc1);
    k_finalize<2><<<NN, 128>>>(acc1, g1b, n1g, n1b, h1);

    // GAT layer 2
    k_gemm<<<dim3(2, cdiv(NN, BM)), 256>>>(h1, g2wl, xl2, NN, HID, HID);
    k_gemm<<<dim3(2, cdiv(NN, BM)), 256>>>(h1, g2wr, xr2, NN, HID, HID);
    k_gat_logits<128, 1><<<2048, 128>>>(xl2, xr2, ea, loop, g2we, g2att, src, dst, logit2, m2);
    k_softmax_e<1><<<cdiv((long)E2T, 256), 256>>>(logit2, m2, den2, dst);
    k_gat_aggregate<128, 1><<<cdiv((long)E2T * 32, 256), 256>>>(xl2, logit2, den2, src, dst, acc2);
    k_finalize<1><<<NN, 128>>>(acc2, g2b, n2g, n2b, h2);

    // classifier (persistent: one block per SM, weights loaded once)
    cudaFuncSetAttribute(k_classifier, cudaFuncAttributeMaxDynamicSharedMemorySize,
                         CLS_SMEM_FLOATS * sizeof(float));
    k_classifier<<<148, 256, CLS_SMEM_FLOATS * sizeof(float)>>>(
        h2, ea, src, dst, c1w, c1b, c2w, c2b, c3w, c3b, out);
}

// round 3
// speedup vs baseline: 1.5238x; 1.2888x over previous
#include <cuda_runtime.h>
#include <math.h>
#include <float.h>

#define NN 50000
#define EE 400000
#define E2T (EE + NN)
#define ND 128
#define ED 64
#define HID 128
#define GIN 258
#define CIN 320

typedef unsigned long long ull;

// ---------------- packed f32x2 helpers ----------------
__device__ __forceinline__ ull pk2(float lo, float hi) {
    ull r; asm("mov.b64 %0,{%1,%2};" : "=l"(r) : "f"(lo), "f"(hi)); return r;
}
__device__ __forceinline__ ull dup2(float v) { return pk2(v, v); }
__device__ __forceinline__ void upk2(ull p, float& lo, float& hi) {
    asm("mov.b64 {%0,%1},%2;" : "=f"(lo), "=f"(hi) : "l"(p));
}
__device__ __forceinline__ ull ffma2(ull a, ull b, ull c) {
    ull d; asm("fma.rn.f32x2 %0,%1,%2,%3;" : "=l"(d) : "l"(a), "l"(b), "l"(c)); return d;
}

// ---------------- scratch ----------------
__device__ float g_xsum_out[NN * ND];
__device__ float g_xsum_in [NN * ND];
__device__ int   g_deg_out [NN];
__device__ int   g_deg_in  [NN];
__device__ float g_loop    [NN * ED];
__device__ float g_xi      [NN * GIN];
__device__ float g_xl1     [NN * 256];
__device__ float g_xr1     [NN * 256];
__device__ float g_logit1  [E2T * 2];
__device__ float g_m1      [NN * 2];
__device__ float g_den1    [NN * 2];
__device__ float g_acc1    [NN * 256];
__device__ float g_h1      [NN * HID];
__device__ float g_xl2     [NN * HID];
__device__ float g_xr2     [NN * HID];
__device__ float g_logit2  [E2T];
__device__ float g_m2      [NN];
__device__ float g_den2    [NN];
__device__ float g_acc2    [NN * HID];
__device__ float g_h2      [NN * HID];

// ---------------- helpers ----------------
__device__ __forceinline__ void atomicMaxF(float* addr, float val) {
    int* ia = (int*)addr;
    int old = *ia;
    while (__int_as_float(old) < val) {
        int assumed = old;
        old = atomicCAS(ia, assumed, __float_as_int(val));
        if (old == assumed) break;
    }
}

__global__ void k_fill_neg(float* p, int n) {
    int i = blockIdx.x * blockDim.x + threadIdx.x;
    if (i < n) p[i] = -FLT_MAX;
}

// ---------------- stage 1+2 fused: embed + scatter + degrees + loop sums ----------------
__global__ void k_embed_scatter(const int* __restrict__ src, const int* __restrict__ dst,
                                const float* __restrict__ ea,
                                const float* __restrict__ epw, const float* __restrict__ epb,
                                float* __restrict__ xsum_out, float* __restrict__ xsum_in,
                                int* __restrict__ deg_out, int* __restrict__ deg_in,
                                float* __restrict__ loop) {
    __shared__ float4 wsh[ED * 32];
    __shared__ float4 bsh4[32];
    __shared__ float  easm[16][ED];
    int tid = threadIdx.x;
    for (int i = tid; i < ED * 32; i += 256) wsh[i] = ((const float4*)epw)[i];
    if (tid < 32) bsh4[tid] = ((const float4*)epb)[tid];
    __syncthreads();
    const ulonglong2* wsh2 = (const ulonglong2*)wsh;
    int sub = tid >> 5;
    int q   = tid & 31;
    for (int base = blockIdx.x * 16; base < EE; base += gridDim.x * 16) {
        #pragma unroll
        for (int r = 0; r < 4; r++) {
            int idx = tid + r * 256;
            int ee = base + (idx >> 6);
            if (ee < EE) easm[idx >> 6][idx & 63] = ea[(size_t)ee * ED + (idx & 63)];
        }
        __syncthreads();
        {
            int e_loc = tid >> 4, q2 = tid & 15;
            int e = base + e_loc;
            if (e < EE) {
                int d = dst[e];
                if (q2 == 0) {
                    atomicAdd(&deg_in[d], 1);
                    atomicAdd(&deg_out[src[e]], 1);
                }
                float4 v = ((const float4*)easm[e_loc])[q2];
                atomicAdd((float4*)(loop + (size_t)d * ED + q2 * 4), v);
            }
        }
        int e0 = base + sub, e1 = base + sub + 8;
        float4 bb = bsh4[q];
        ull a0[2] = { pk2(bb.x, bb.y), pk2(bb.z, bb.w) };
        ull a1[2] = { a0[0], a0[1] };
        const float* er0 = easm[sub];
        const float* er1 = easm[sub + 8];
        #pragma unroll
        for (int k = 0; k < ED; k++) {
            ulonglong2 w2 = wsh2[k * 32 + q];
            ull b0 = dup2(er0[k]), b1 = dup2(er1[k]);
            a0[0] = ffma2(b0, w2.x, a0[0]); a0[1] = ffma2(b0, w2.y, a0[1]);
            a1[0] = ffma2(b1, w2.x, a1[0]); a1[1] = ffma2(b1, w2.y, a1[1]);
        }
        if (e0 < EE) {
            float4 o; upk2(a0[0], o.x, o.y); upk2(a0[1], o.z, o.w);
            o.x = fmaxf(o.x, 0.f); o.y = fmaxf(o.y, 0.f); o.z = fmaxf(o.z, 0.f); o.w = fmaxf(o.w, 0.f);
            int s = src[e0], d = dst[e0];
            atomicAdd((float4*)(xsum_out + (size_t)s * ND + q * 4), o);
            atomicAdd((float4*)(xsum_in  + (size_t)d * ND + q * 4), o);
        }
        if (e1 < EE) {
            float4 o; upk2(a1[0], o.x, o.y); upk2(a1[1], o.z, o.w);
            o.x = fmaxf(o.x, 0.f); o.y = fmaxf(o.y, 0.f); o.z = fmaxf(o.z, 0.f); o.w = fmaxf(o.w, 0.f);
            int s = src[e1], d = dst[e1];
            atomicAdd((float4*)(xsum_out + (size_t)s * ND + q * 4), o);
            atomicAdd((float4*)(xsum_in  + (size_t)d * ND + q * 4), o);
        }
        __syncthreads();
    }
}

// ---------------- stage 3: build xi, finalize loop_attr ----------------
__global__ void k_build_xi(const float* __restrict__ node_stats,
                           const float* __restrict__ xsum_out, const float* __restrict__ xsum_in,
                           const int* __restrict__ deg_out, const int* __restrict__ deg_in,
                           float* __restrict__ xi) {
    int tid = blockIdx.x * blockDim.x + threadIdx.x;
    if (tid >= NN * GIN) return;
    int i = tid / GIN, j = tid - i * GIN;
    float v;
    if (j < 128)      v = xsum_out[i * 128 + j]        / fmaxf((float)deg_out[i], 1.f);
    else if (j < 256) v = xsum_in [i * 128 + (j - 128)] / fmaxf((float)deg_in [i], 1.f);
    else              v = node_stats[i * 2 + (j - 256)];
    xi[tid] = v;
}

__global__ void k_loop_div(float* __restrict__ loop, const int* __restrict__ deg_in) {
    int tid = blockIdx.x * blockDim.x + threadIdx.x;
    if (tid >= NN * ED) return;
    int i = tid >> 6;
    loop[tid] = loop[tid] / fmaxf((float)deg_in[i], 1.f);
}

// ---------------- fp32 tiled GEMM with FFMA2 ----------------
#define BM 64
#define BN 64
#define BKK 16
__global__ void k_gemm(const float* __restrict__ A, const float* __restrict__ B,
                       float* __restrict__ C, int M, int K, int Nc) {
    __shared__ float As[BKK][BM + 4];
    __shared__ float Bs[BKK][BN + 4];
    int brow = blockIdx.y * BM, bcol = blockIdx.x * BN;
    int tid = threadIdx.x;
    int tr = tid >> 4, tc = tid & 15;
    ull accp[4][2];
    #pragma unroll
    for (int i = 0; i < 4; i++) { accp[i][0] = 0ull; accp[i][1] = 0ull; }
    for (int k0 = 0; k0 < K; k0 += BKK) {
        for (int i = tid; i < BM * BKK; i += 256) {
            int r = i >> 4, c = i & 15;
            int gr = brow + r, gc = k0 + c;
            As[c][r] = (gr < M && gc < K) ? A[(size_t)gr * K + gc] : 0.f;
        }
        for (int i = tid; i < BKK * BN; i += 256) {
            int r = i >> 6, c = i & 63;
            int gr = k0 + r, gc = bcol + c;
            Bs[r][c] = (gr < K && gc < Nc) ? B[(size_t)gr * Nc + gc] : 0.f;
        }
        __syncthreads();
        #pragma unroll
        for (int kk = 0; kk < BKK; kk++) {
            float4 a4 = *(const float4*)&As[kk][tr * 4];
            ulonglong2 b2 = *(const ulonglong2*)&Bs[kk][tc * 4];
            ull ap0 = dup2(a4.x), ap1 = dup2(a4.y), ap2 = dup2(a4.z), ap3 = dup2(a4.w);
            accp[0][0] = ffma2(ap0, b2.x, accp[0][0]); accp[0][1] = ffma2(ap0, b2.y, accp[0][1]);
            accp[1][0] = ffma2(ap1, b2.x, accp[1][0]); accp[1][1] = ffma2(ap1, b2.y, accp[1][1]);
            accp[2][0] = ffma2(ap2, b2.x, accp[2][0]); accp[2][1] = ffma2(ap2, b2.y, accp[2][1]);
            accp[3][0] = ffma2(ap3, b2.x, accp[3][0]); accp[3][1] = ffma2(ap3, b2.y, accp[3][1]);
        }
        __syncthreads();
    }
    #pragma unroll
    for (int i = 0; i < 4; i++) {
        int row = brow + tr * 4 + i;
        if (row >= M) continue;
        float v[4];
        upk2(accp[i][0], v[0], v[1]); upk2(accp[i][1], v[2], v[3]);
        #pragma unroll
        for (int j = 0; j < 4; j++) {
            int col = bcol + tc * 4 + j;
            if (col < Nc) C[(size_t)row * Nc + col] = v[j];
        }
    }
}

// ---------------- GATv2 pass A: logits + segment max (warp-chunked, batched) ---------
// warp owns a 32-wide output chunk; NWE = OUT/32 warps per edge; 8 warps total.
template <int OUT, int H>
__global__ void k_gat_logits(const float* __restrict__ xl, const float* __restrict__ xr,
                             const float* __restrict__ ea, const float* __restrict__ loop,
                             const float* __restrict__ we, const float* __restrict__ att,
                             const int* __restrict__ src, const int* __restrict__ dst,
                             float* __restrict__ logit, float* __restrict__ m) {
    const int NWE = OUT / 32;           // warps per edge (8 or 4)
    const int NG  = 8 / NWE;            // concurrent edge groups (1 or 2)
    const int EPI = NG * 8;             // edges per iteration (8 or 16)
    __shared__ __align__(16) float easm[EPI][ED];
    __shared__ float part[EPI][8];
    __shared__ int   ssm[EPI], dsm[EPI];
    int t = threadIdx.x, w = t >> 5, lane = t & 31;
    int g = w / NWE, c = w % NWE;
    int outi = c * 32 + lane;
    ull wp[ED / 2];
    #pragma unroll
    for (int k2 = 0; k2 < ED / 2; k2++)
        wp[k2] = pk2(we[(2 * k2) * OUT + outi], we[(2 * k2 + 1) * OUT + outi]);
    float attv = att[outi];
    for (int base = blockIdx.x * EPI; base < E2T; base += gridDim.x * EPI) {
        // stage edge rows + indices
        for (int idx = t; idx < EPI * ED; idx += 256) {
            int ei = idx >> 6, k = idx & 63;
            int e = base + ei;
            if (e < EE)       easm[ei][k] = ea[(size_t)e * ED + k];
            else if (e < E2T) easm[ei][k] = loop[(size_t)(e - EE) * ED + k];
        }
        if (t < EPI) {
            int e = base + t;
            if (e < EE)       { ssm[t] = src[e]; dsm[t] = dst[e]; }
            else if (e < E2T) { ssm[t] = dsm[t] = e - EE; }
        }
        __syncthreads();
        #pragma unroll
        for (int i = 0; i < 8; i++) {
            int ei = g * 8 + i;
            int e = base + ei;
            if (e >= E2T) break;
            int s = ssm[ei], d = dsm[ei];
            const ull* ep = (const ull*)easm[ei];
            ull acc2 = 0ull;
            #pragma unroll
            for (int k2 = 0; k2 < ED / 2; k2++) acc2 = ffma2(wp[k2], ep[k2], acc2);
            float lo, hi; upk2(acc2, lo, hi);
            float v = lo + hi + xl[(size_t)s * OUT + outi] + xr[(size_t)d * OUT + outi];
            v = v > 0.f ? v : 0.2f * v;
            v *= attv;
            #pragma unroll
            for (int o = 16; o; o >>= 1) v += __shfl_xor_sync(0xffffffffu, v, o);
            if (lane == 0) part[ei][c] = v;
        }
        __syncthreads();
        if (t < EPI * H) {
            int ei = t / H, h = t - ei * H;
            int e = base + ei;
            if (e < E2T) {
                int c0 = (H == 2) ? h * 4 : 0;
                float lg = part[ei][c0] + part[ei][c0 + 1] + part[ei][c0 + 2] + part[ei][c0 + 3];
                if (NWE == 8 && H == 1) lg += part[ei][4] + part[ei][5] + part[ei][6] + part[ei][7];
                logit[(size_t)e * H + h] = lg;
                atomicMaxF(&m[dsm[ei] * H + h], lg);
            }
        }
        __syncthreads();
    }
}

// ---------------- GATv2 pass B ----------------
template <int H>
__global__ void k_softmax_e(float* __restrict__ logit, const float* __restrict__ m,
                            float* __restrict__ den, const int* __restrict__ dst) {
    int tid = blockIdx.x * blockDim.x + threadIdx.x;
    if (tid >= E2T * H) return;
    int e = tid / H, h = tid - e * H;
    int d = (e < EE) ? dst[e] : (e - EE);
    float mm = m[d * H + h];
    if (mm == -FLT_MAX) mm = 0.f;
    float a = expf(logit[tid] - mm);
    logit[tid] = a;
    atomicAdd(&den[d * H + h], a);
}

// ---------------- GATv2 pass C ----------------
template <int OUT, int H>
__global__ void k_gat_aggregate(const float* __restrict__ xl, const float* __restrict__ logit,
                                const float* __restrict__ den, const int* __restrict__ src,
                                const int* __restrict__ dst, float* __restrict__ acc) {
    const int Q = OUT / 4;
    int tid = blockIdx.x * blockDim.x + threadIdx.x;
    if (tid >= E2T * Q) return;
    int e = tid / Q, q = tid - e * Q;
    int s, d;
    if (e < EE) { s = src[e]; d = dst[e]; } else { s = d = e - EE; }
    int h = (q * 4) >> 7;
    float a = logit[(size_t)e * H + h];
    float dn = den[d * H + h];
    float coef = a / fmaxf(dn, 1e-16f);
    float4 x = *(const float4*)(xl + (size_t)s * OUT + q * 4);
    x.x *= coef; x.y *= coef; x.z *= coef; x.w *= coef;
    atomicAdd((float4*)(acc + (size_t)d * OUT + q * 4), x);
}

// ---------------- finalize ----------------
template <int H>
__global__ void k_finalize(const float* __restrict__ acc, const float* __restrict__ bias,
                           const float* __restrict__ g, const float* __restrict__ b,
                           float* __restrict__ out) {
    __shared__ float sb[4];
    int i = blockIdx.x, t = threadIdx.x;
    float v;
    if (H == 2) v = 0.5f * (acc[(size_t)i * 256 + t] + acc[(size_t)i * 256 + 128 + t]) + bias[t];
    else        v = acc[(size_t)i * 128 + t] + bias[t];
    float s = v;
    #pragma unroll
    for (int o = 16; o; o >>= 1) s += __shfl_xor_sync(0xffffffffu, s, o);
    if ((t & 31) == 0) sb[t >> 5] = s;
    __syncthreads();
    float mu = (sb[0] + sb[1] + sb[2] + sb[3]) * (1.f / 128.f);
    __syncthreads();
    float dv = v - mu;
    s = dv * dv;
    #pragma unroll
    for (int o = 16; o; o >>= 1) s += __shfl_xor_sync(0xffffffffu, s, o);
    if ((t & 31) == 0) sb[t >> 5] = s;
    __syncthreads();
    float var = (sb[0] + sb[1] + sb[2] + sb[3]) * (1.f / 128.f);
    float o2 = dv * rsqrtf(var + 1e-5f) * g[t] + b[t];
    out[(size_t)i * 128 + t] = o2 > 0.f ? o2 : (expf(o2) - 1.f);
}

// ---------------- classifier: per-edge 320->128->64->1 MLP, FFMA2, EB=6 ----------------
#define CLS_EB 6
#define CLS_SMEM_FLOATS (CIN*HID + HID*64 + 64 + 128 + 64)
__global__ void __launch_bounds__(256, 1)
k_classifier(const float* __restrict__ h2, const float* __restrict__ ea,
             const int* __restrict__ src, const int* __restrict__ dst,
             const float* __restrict__ c1w, const float* __restrict__ c1b,
             const float* __restrict__ c2w, const float* __restrict__ c2b,
             const float* __restrict__ c3w, const float* __restrict__ c3b,
             float* __restrict__ out) {
    extern __shared__ float sm[];
    float* c1s = sm;
    float* c2s = c1s + CIN * HID;
    float* c3s = c2s + HID * 64;
    float* b1s = c3s + 64;
    float* b2s = b1s + 128;
    int tid = threadIdx.x;
    for (int i = tid; i < CIN * HID; i += 256) c1s[i] = c1w[i];
    for (int i = tid; i < HID * 64; i += 256) c2s[i] = c2w[i];
    if (tid < 64)  c3s[tid] = c3w[tid];
    if (tid < 128) b1s[tid] = c1b[tid];
    if (tid < 64)  b2s[tid] = c2b[tid];
    __syncthreads();
    const ulonglong2* c1p = (const ulonglong2*)c1s;
    const ull* c2p = (const ull*)c2s;
    float c3bv = c3b[0];
    int warp = tid >> 5, lane = tid & 31;
    const int stride = gridDim.x * 8 * CLS_EB;
    for (int e0 = (blockIdx.x * 8 + warp) * CLS_EB; e0 < EE; e0 += stride) {
        float er[CLS_EB][10];
        #pragma unroll
        for (int ei = 0; ei < CLS_EB; ei++) {
            int e = e0 + ei;
            if (e < EE) {
                int s = src[e], d = dst[e];
                #pragma unroll
                for (int r = 0; r < 4; r++) er[ei][r]     = h2[(size_t)s * HID + r * 32 + lane];
                #pragma unroll
                for (int r = 0; r < 4; r++) er[ei][4 + r] = h2[(size_t)d * HID + r * 32 + lane];
                er[ei][8] = ea[(size_t)e * ED + lane];
                er[ei][9] = ea[(size_t)e * ED + 32 + lane];
            } else {
                #pragma unroll
                for (int r = 0; r < 10; r++) er[ei][r] = 0.f;
            }
        }
        // layer 1: lane owns output cols 4*lane..4*lane+3 (as 2 f32x2 pairs)
        ull a1p[CLS_EB][2];
        {
            float4 bb4 = ((const float4*)b1s)[lane];
            ull p0 = pk2(bb4.x, bb4.y), p1 = pk2(bb4.z, bb4.w);
            #pragma unroll
            for (int ei = 0; ei < CLS_EB; ei++) { a1p[ei][0] = p0; a1p[ei][1] = p1; }
        }
        #pragma unroll
        for (int r = 0; r < 10; r++) {
            #pragma unroll
            for (int kk = 0; kk < 32; kk++) {
                ulonglong2 w2 = c1p[(r * 32 + kk) * 32 + lane];
                #pragma unroll
                for (int ei = 0; ei < CLS_EB; ei++) {
                    ull bp = dup2(__shfl_sync(0xffffffffu, er[ei][r], kk));
                    a1p[ei][0] = ffma2(bp, w2.x, a1p[ei][0]);
                    a1p[ei][1] = ffma2(bp, w2.y, a1p[ei][1]);
                }
            }
        }
        float a1f[CLS_EB][4];
        #pragma unroll
        for (int ei = 0; ei < CLS_EB; ei++) {
            upk2(a1p[ei][0], a1f[ei][0], a1f[ei][1]);
            upk2(a1p[ei][1], a1f[ei][2], a1f[ei][3]);
            #pragma unroll
            for (int c = 0; c < 4; c++) a1f[ei][c] = fmaxf(a1f[ei][c], 0.f);
        }
        // layer 2: lane owns output cols 2*lane, 2*lane+1 (1 f32x2 pair)
        ull a2p[CLS_EB];
        {
            float2 bb2 = ((const float2*)b2s)[lane];
            ull p = pk2(bb2.x, bb2.y);
            #pragma unroll
            for (int ei = 0; ei < CLS_EB; ei++) a2p[ei] = p;
        }
        #pragma unroll
        for (int kq = 0; kq < 32; kq++) {
            #pragma unroll
            for (int c = 0; c < 4; c++) {
                ull w2 = c2p[(kq * 4 + c) * 32 + lane];
                #pragma unroll
                for (int ei = 0; ei < CLS_EB; ei++) {
                    ull bp = dup2(__shfl_sync(0xffffffffu, a1f[ei][c], kq));
                    a2p[ei] = ffma2(bp, w2, a2p[ei]);
                }
            }
        }
        // layer 3
        float w3a = c3s[lane * 2], w3b = c3s[lane * 2 + 1];
        #pragma unroll
        for (int ei = 0; ei < CLS_EB; ei++) {
            float x, y; upk2(a2p[ei], x, y);
            float v = fmaxf(x, 0.f) * w3a + fmaxf(y, 0.f) * w3b;
            #pragma unroll
            for (int o = 16; o; o >>= 1) v += __shfl_xor_sync(0xffffffffu, v, o);
            int e = e0 + ei;
            if (lane == 0 && e < EE) out[e] = v + c3bv;
        }
    }
}

// ---------------- launch ----------------
static inline int cdiv(long a, long b) { return (int)((a + b - 1) / b); }

extern "C" void kernel_launch(void* const* d_in, const int* in_sizes, int n_in,
                              void* d_out, int out_size) {
    const float* node_stats = (const float*)d_in[1];
    const int*   ei   = (const int*)d_in[2];
    const int*   src  = ei;
    const int*   dst  = ei + EE;
    const float* ea   = (const float*)d_in[3];
    const float* epw  = (const float*)d_in[4];
    const float* epb  = (const float*)d_in[5];
    const float* g1wl = (const float*)d_in[6];
    const float* g1wr = (const float*)d_in[7];
    const float* g1we = (const float*)d_in[8];
    const float* g1att= (const float*)d_in[9];
    const float* g1b  = (const float*)d_in[10];
    const float* n1g  = (const float*)d_in[11];
    const float* n1b  = (const float*)d_in[12];
    const float* g2wl = (const float*)d_in[13];
    const float* g2wr = (const float*)d_in[14];
    const float* g2we = (const float*)d_in[15];
    const float* g2att= (const float*)d_in[16];
    const float* g2b  = (const float*)d_in[17];
    const float* n2g  = (const float*)d_in[18];
    const float* n2b  = (const float*)d_in[19];
    const float* c1w  = (const float*)d_in[20];
    const float* c1b  = (const float*)d_in[21];
    const float* c2w  = (const float*)d_in[22];
    const float* c2b  = (const float*)d_in[23];
    const float* c3w  = (const float*)d_in[24];
    const float* c3b  = (const float*)d_in[25];
    float* out = (float*)d_out;

    float *xsum_out, *xsum_in, *loop, *xi, *xl1, *xr1, *logit1, *m1, *den1, *acc1, *h1;
    float *xl2, *xr2, *logit2, *m2, *den2, *acc2, *h2;
    int *deg_out, *deg_in;
    cudaGetSymbolAddress((void**)&xsum_out, g_xsum_out);
    cudaGetSymbolAddress((void**)&xsum_in,  g_xsum_in);
    cudaGetSymbolAddress((void**)&deg_out,  g_deg_out);
    cudaGetSymbolAddress((void**)&deg_in,   g_deg_in);
    cudaGetSymbolAddress((void**)&loop,     g_loop);
    cudaGetSymbolAddress((void**)&xi,       g_xi);
    cudaGetSymbolAddress((void**)&xl1,      g_xl1);
    cudaGetSymbolAddress((void**)&xr1,      g_xr1);
    cudaGetSymbolAddress((void**)&logit1,   g_logit1);
    cudaGetSymbolAddress((void**)&m1,       g_m1);
    cudaGetSymbolAddress((void**)&den1,     g_den1);
    cudaGetSymbolAddress((void**)&acc1,     g_acc1);
    cudaGetSymbolAddress((void**)&h1,       g_h1);
    cudaGetSymbolAddress((void**)&xl2,      g_xl2);
    cudaGetSymbolAddress((void**)&xr2,      g_xr2);
    cudaGetSymbolAddress((void**)&logit2,   g_logit2);
    cudaGetSymbolAddress((void**)&m2,       g_m2);
    cudaGetSymbolAddress((void**)&den2,     g_den2);
    cudaGetSymbolAddress((void**)&acc2,     g_acc2);
    cudaGetSymbolAddress((void**)&h2,       g_h2);

    cudaMemsetAsync(xsum_out, 0, sizeof(float) * NN * ND);
    cudaMemsetAsync(xsum_in,  0, sizeof(float) * NN * ND);
    cudaMemsetAsync(deg_out,  0, sizeof(int) * NN);
    cudaMemsetAsync(deg_in,   0, sizeof(int) * NN);
    cudaMemsetAsync(loop,     0, sizeof(float) * NN * ED);
    cudaMemsetAsync(den1,     0, sizeof(float) * NN * 2);
    cudaMemsetAsync(den2,     0, sizeof(float) * NN);
    cudaMemsetAsync(acc1,     0, sizeof(float) * NN * 256);
    cudaMemsetAsync(acc2,     0, sizeof(float) * NN * 128);
    k_fill_neg<<<cdiv(NN * 2, 256), 256>>>(m1, NN * 2);
    k_fill_neg<<<cdiv(NN, 256), 256>>>(m2, NN);

    k_embed_scatter<<<2048, 256>>>(src, dst, ea, epw, epb, xsum_out, xsum_in,
                                   deg_out, deg_in, loop);
    k_build_xi<<<cdiv((long)NN * GIN, 256), 256>>>(node_stats, xsum_out, xsum_in, deg_out, deg_in, xi);
    k_loop_div<<<cdiv((long)NN * ED, 256), 256>>>(loop, deg_in);

    // GAT layer 1
    k_gemm<<<dim3(4, cdiv(NN, BM)), 256>>>(xi, g1wl, xl1, NN, GIN, 256);
    k_gemm<<<dim3(4, cdiv(NN, BM)), 256>>>(xi, g1wr, xr1, NN, GIN, 256);
    k_gat_logits<256, 2><<<2048, 256>>>(xl1, xr1, ea, loop, g1we, g1att, src, dst, logit1, m1);
    k_softmax_e<2><<<cdiv((long)E2T * 2, 256), 256>>>(logit1, m1, den1, dst);
    k_gat_aggregate<256, 2><<<cdiv((long)E2T * 64, 256), 256>>>(xl1, logit1, den1, src, dst, acc1);
    k_finalize<2><<<NN, 128>>>(acc1, g1b, n1g, n1b, h1);

    // GAT layer 2
    k_gemm<<<dim3(2, cdiv(NN, BM)), 256>>>(h1, g2wl, xl2, NN, HID, HID);
    k_gemm<<<dim3(2, cdiv(NN, BM)), 256>>>(h1, g2wr, xr2, NN, HID, HID);
    k_gat_logits<128, 1><<<2048, 256>>>(xl2, xr2, ea, loop, g2we, g2att, src, dst, logit2, m2);
    k_softmax_e<1><<<cdiv((long)E2T, 256), 256>>>(logit2, m2, den2, dst);
    k_gat_aggregate<128, 1><<<cdiv((long)E2T * 32, 256), 256>>>(xl2, logit2, den2, src, dst, acc2);
    k_finalize<1><<<NN, 128>>>(acc2, g2b, n2g, n2b, h2);

    // classifier
    cudaFuncSetAttribute(k_classifier, cudaFuncAttributeMaxDynamicSharedMemorySize,
                         CLS_SMEM_FLOATS * sizeof(float));
    k_classifier<<<148, 256, CLS_SMEM_FLOATS * sizeof(float)>>>(
        h2, ea, src, dst, c1w, c1b, c2w, c2b, c3w, c3b, out);
}

// round 4
// speedup vs baseline: 1.6208x; 1.0637x over previous
#include <cuda_runtime.h>
#include <math.h>
#include <float.h>

#define NN 50000
#define EE 400000
#define E2T (EE + NN)
#define ND 128
#define ED 64
#define HID 128
#define GIN 258
#define CIN 320

typedef unsigned long long ull;

// ---------------- packed f32x2 helpers ----------------
__device__ __forceinline__ ull pk2(float lo, float hi) {
    ull r; asm("mov.b64 %0,{%1,%2};" : "=l"(r) : "f"(lo), "f"(hi)); return r;
}
__device__ __forceinline__ ull dup2(float v) { return pk2(v, v); }
__device__ __forceinline__ void upk2(ull p, float& lo, float& hi) {
    asm("mov.b64 {%0,%1},%2;" : "=f"(lo), "=f"(hi) : "l"(p));
}
__device__ __forceinline__ ull ffma2(ull a, ull b, ull c) {
    ull d; asm("fma.rn.f32x2 %0,%1,%2,%3;" : "=l"(d) : "l"(a), "l"(b), "l"(c)); return d;
}

// ---------------- scratch ----------------
__device__ float g_xsum_out[NN * ND];
__device__ float g_xsum_in [NN * ND];
__device__ int   g_deg_out [NN];
__device__ int   g_deg_in  [NN];
__device__ float g_loop    [NN * ED];
__device__ float g_xi      [NN * GIN];
__device__ float g_xl1     [NN * 256];
__device__ float g_xr1     [NN * 256];
__device__ float g_logit1  [E2T * 2];   // sorted by dst (via ipos)
__device__ float g_h1      [NN * HID];
__device__ float g_xl2     [NN * HID];
__device__ float g_xr2     [NN * HID];
__device__ float g_logit2  [E2T];       // sorted by dst
__device__ float g_h2      [NN * HID];
__device__ int   g_rowptr  [NN + 1];
__device__ int   g_cursor  [NN];
__device__ int   g_psrc    [E2T];
__device__ int   g_ipos    [E2T];

// ---------------- stage 1+2 fused: embed + scatter + degrees + loop sums ----------------
__global__ void k_embed_scatter(const int* __restrict__ src, const int* __restrict__ dst,
                                const float* __restrict__ ea,
                                const float* __restrict__ epw, const float* __restrict__ epb,
                                float* __restrict__ xsum_out, float* __restrict__ xsum_in,
                                int* __restrict__ deg_out, int* __restrict__ deg_in,
                                float* __restrict__ loop) {
    __shared__ float4 wsh[ED * 32];
    __shared__ float4 bsh4[32];
    __shared__ float  easm[16][ED];
    int tid = threadIdx.x;
    for (int i = tid; i < ED * 32; i += 256) wsh[i] = ((const float4*)epw)[i];
    if (tid < 32) bsh4[tid] = ((const float4*)epb)[tid];
    __syncthreads();
    const ulonglong2* wsh2 = (const ulonglong2*)wsh;
    int sub = tid >> 5;
    int q   = tid & 31;
    for (int base = blockIdx.x * 16; base < EE; base += gridDim.x * 16) {
        #pragma unroll
        for (int r = 0; r < 4; r++) {
            int idx = tid + r * 256;
            int ee = base + (idx >> 6);
            if (ee < EE) easm[idx >> 6][idx & 63] = ea[(size_t)ee * ED + (idx & 63)];
        }
        __syncthreads();
        {
            int e_loc = tid >> 4, q2 = tid & 15;
            int e = base + e_loc;
            if (e < EE) {
                int d = dst[e];
                if (q2 == 0) {
                    atomicAdd(&deg_in[d], 1);
                    atomicAdd(&deg_out[src[e]], 1);
                }
                float4 v = ((const float4*)easm[e_loc])[q2];
                atomicAdd((float4*)(loop + (size_t)d * ED + q2 * 4), v);
            }
        }
        int e0 = base + sub, e1 = base + sub + 8;
        float4 bb = bsh4[q];
        ull a0[2] = { pk2(bb.x, bb.y), pk2(bb.z, bb.w) };
        ull a1[2] = { a0[0], a0[1] };
        const float* er0 = easm[sub];
        const float* er1 = easm[sub + 8];
        #pragma unroll
        for (int k = 0; k < ED; k++) {
            ulonglong2 w2 = wsh2[k * 32 + q];
            ull b0 = dup2(er0[k]), b1 = dup2(er1[k]);
            a0[0] = ffma2(b0, w2.x, a0[0]); a0[1] = ffma2(b0, w2.y, a0[1]);
            a1[0] = ffma2(b1, w2.x, a1[0]); a1[1] = ffma2(b1, w2.y, a1[1]);
        }
        if (e0 < EE) {
            float4 o; upk2(a0[0], o.x, o.y); upk2(a0[1], o.z, o.w);
            o.x = fmaxf(o.x, 0.f); o.y = fmaxf(o.y, 0.f); o.z = fmaxf(o.z, 0.f); o.w = fmaxf(o.w, 0.f);
            int s = src[e0], d = dst[e0];
            atomicAdd((float4*)(xsum_out + (size_t)s * ND + q * 4), o);
            atomicAdd((float4*)(xsum_in  + (size_t)d * ND + q * 4), o);
        }
        if (e1 < EE) {
            float4 o; upk2(a1[0], o.x, o.y); upk2(a1[1], o.z, o.w);
            o.x = fmaxf(o.x, 0.f); o.y = fmaxf(o.y, 0.f); o.z = fmaxf(o.z, 0.f); o.w = fmaxf(o.w, 0.f);
            int s = src[e1], d = dst[e1];
            atomicAdd((float4*)(xsum_out + (size_t)s * ND + q * 4), o);
            atomicAdd((float4*)(xsum_in  + (size_t)d * ND + q * 4), o);
        }
        __syncthreads();
    }
}

// ---------------- stage 3: build xi, finalize loop_attr ----------------
__global__ void k_build_xi(const float* __restrict__ node_stats,
                           const float* __restrict__ xsum_out, const float* __restrict__ xsum_in,
                           const int* __restrict__ deg_out, const int* __restrict__ deg_in,
                           float* __restrict__ xi) {
    int tid = blockIdx.x * blockDim.x + threadIdx.x;
    if (tid >= NN * GIN) return;
    int i = tid / GIN, j = tid - i * GIN;
    float v;
    if (j < 128)      v = xsum_out[i * 128 + j]        / fmaxf((float)deg_out[i], 1.f);
    else if (j < 256) v = xsum_in [i * 128 + (j - 128)] / fmaxf((float)deg_in [i], 1.f);
    else              v = node_stats[i * 2 + (j - 256)];
    xi[tid] = v;
}

__global__ void k_loop_div(float* __restrict__ loop, const int* __restrict__ deg_in) {
    int tid = blockIdx.x * blockDim.x + threadIdx.x;
    if (tid >= NN * ED) return;
    int i = tid >> 6;
    loop[tid] = loop[tid] / fmaxf((float)deg_in[i], 1.f);
}

// ---------------- CSR build: prefix scan (rows sized deg_in+1 for self-loop) ----------
__global__ void k_prefix(const int* __restrict__ deg_in, int* __restrict__ rowptr,
                         int* __restrict__ cursor) {
    __shared__ int ssum[1024];
    const int CH = (NN + 1023) / 1024;
    int t = threadIdx.x;
    int base = t * CH;
    int s = 0;
    for (int i = 0; i < CH; i++) {
        int n = base + i;
        if (n < NN) s += deg_in[n] + 1;
    }
    ssum[t] = s;
    __syncthreads();
    for (int off = 1; off < 1024; off <<= 1) {
        int v = (t >= off) ? ssum[t - off] : 0;
        __syncthreads();
        ssum[t] += v;
        __syncthreads();
    }
    int run = (t == 0) ? 0 : ssum[t - 1];
    for (int i = 0; i < CH; i++) {
        int n = base + i;
        if (n < NN) {
            rowptr[n] = run;
            cursor[n] = run;
            run += deg_in[n] + 1;
        }
    }
    if (t == 1023) rowptr[NN] = E2T;
}

__global__ void k_perm(const int* __restrict__ src, const int* __restrict__ dst,
                       int* __restrict__ cursor, int* __restrict__ psrc,
                       int* __restrict__ ipos) {
    int e = blockIdx.x * blockDim.x + threadIdx.x;
    if (e < EE) {
        int pos = atomicAdd(&cursor[dst[e]], 1);
        psrc[pos] = src[e];
        ipos[e] = pos;
    } else if (e < E2T) {
        int i = e - EE;
        int pos = atomicAdd(&cursor[i], 1);
        psrc[pos] = i;
        ipos[e] = pos;
    }
}

// ---------------- fp32 tiled GEMM with FFMA2 ----------------
#define BM 64
#define BN 64
#define BKK 16
__global__ void k_gemm(const float* __restrict__ A, const float* __restrict__ B,
                       float* __restrict__ C, int M, int K, int Nc) {
    __shared__ float As[BKK][BM + 4];
    __shared__ float Bs[BKK][BN + 4];
    int brow = blockIdx.y * BM, bcol = blockIdx.x * BN;
    int tid = threadIdx.x;
    int tr = tid >> 4, tc = tid & 15;
    ull accp[4][2];
    #pragma unroll
    for (int i = 0; i < 4; i++) { accp[i][0] = 0ull; accp[i][1] = 0ull; }
    for (int k0 = 0; k0 < K; k0 += BKK) {
        for (int i = tid; i < BM * BKK; i += 256) {
            int r = i >> 4, c = i & 15;
            int gr = brow + r, gc = k0 + c;
            As[c][r] = (gr < M && gc < K) ? A[(size_t)gr * K + gc] : 0.f;
        }
        for (int i = tid; i < BKK * BN; i += 256) {
            int r = i >> 6, c = i & 63;
            int gr = k0 + r, gc = bcol + c;
            Bs[r][c] = (gr < K && gc < Nc) ? B[(size_t)gr * Nc + gc] : 0.f;
        }
        __syncthreads();
        #pragma unroll
        for (int kk = 0; kk < BKK; kk++) {
            float4 a4 = *(const float4*)&As[kk][tr * 4];
            ulonglong2 b2 = *(const ulonglong2*)&Bs[kk][tc * 4];
            ull ap0 = dup2(a4.x), ap1 = dup2(a4.y), ap2 = dup2(a4.z), ap3 = dup2(a4.w);
            accp[0][0] = ffma2(ap0, b2.x, accp[0][0]); accp[0][1] = ffma2(ap0, b2.y, accp[0][1]);
            accp[1][0] = ffma2(ap1, b2.x, accp[1][0]); accp[1][1] = ffma2(ap1, b2.y, accp[1][1]);
            accp[2][0] = ffma2(ap2, b2.x, accp[2][0]); accp[2][1] = ffma2(ap2, b2.y, accp[2][1]);
            accp[3][0] = ffma2(ap3, b2.x, accp[3][0]); accp[3][1] = ffma2(ap3, b2.y, accp[3][1]);
        }
        __syncthreads();
    }
    #pragma unroll
    for (int i = 0; i < 4; i++) {
        int row = brow + tr * 4 + i;
        if (row >= M) continue;
        float v[4];
        upk2(accp[i][0], v[0], v[1]); upk2(accp[i][1], v[2], v[3]);
        #pragma unroll
        for (int j = 0; j < 4; j++) {
            int col = bcol + tc * 4 + j;
            if (col < Nc) C[(size_t)row * Nc + col] = v[j];
        }
    }
}

// ---------------- GATv2 pass A: logits -> sorted positions (no atomics) ----------------
template <int OUT, int H>
__global__ void k_gat_logits(const float* __restrict__ xl, const float* __restrict__ xr,
                             const float* __restrict__ ea, const float* __restrict__ loop,
                             const float* __restrict__ we, const float* __restrict__ att,
                             const int* __restrict__ src, const int* __restrict__ dst,
                             const int* __restrict__ ipos, float* __restrict__ logit) {
    const int NWE = OUT / 32;
    const int NG  = 8 / NWE;
    const int EPI = NG * 8;
    __shared__ __align__(16) float easm[EPI][ED];
    __shared__ float part[EPI][8];
    __shared__ int   ssm[EPI], dsm[EPI];
    int t = threadIdx.x, w = t >> 5, lane = t & 31;
    int g = w / NWE, c = w % NWE;
    int outi = c * 32 + lane;
    ull wp[ED / 2];
    #pragma unroll
    for (int k2 = 0; k2 < ED / 2; k2++)
        wp[k2] = pk2(we[(2 * k2) * OUT + outi], we[(2 * k2 + 1) * OUT + outi]);
    float attv = att[outi];
    for (int base = blockIdx.x * EPI; base < E2T; base += gridDim.x * EPI) {
        for (int idx = t; idx < EPI * ED; idx += 256) {
            int ei = idx >> 6, k = idx & 63;
            int e = base + ei;
            if (e < EE)       easm[ei][k] = ea[(size_t)e * ED + k];
            else if (e < E2T) easm[ei][k] = loop[(size_t)(e - EE) * ED + k];
        }
        if (t < EPI) {
            int e = base + t;
            if (e < EE)       { ssm[t] = src[e]; dsm[t] = dst[e]; }
            else if (e < E2T) { ssm[t] = dsm[t] = e - EE; }
        }
        __syncthreads();
        #pragma unroll
        for (int i = 0; i < 8; i++) {
            int ei = g * 8 + i;
            int e = base + ei;
            if (e >= E2T) break;
            int s = ssm[ei], d = dsm[ei];
            const ull* ep = (const ull*)easm[ei];
            ull acc2 = 0ull;
            #pragma unroll
            for (int k2 = 0; k2 < ED / 2; k2++) acc2 = ffma2(wp[k2], ep[k2], acc2);
            float lo, hi; upk2(acc2, lo, hi);
            float v = lo + hi + xl[(size_t)s * OUT + outi] + xr[(size_t)d * OUT + outi];
            v = v > 0.f ? v : 0.2f * v;
            v *= attv;
            #pragma unroll
            for (int o = 16; o; o >>= 1) v += __shfl_xor_sync(0xffffffffu, v, o);
            if (lane == 0) part[ei][c] = v;
        }
        __syncthreads();
        if (t < EPI * H) {
            int ei = t / H, h = t - ei * H;
            int e = base + ei;
            if (e < E2T) {
                int c0 = (H == 2) ? h * 4 : 0;
                float lg = part[ei][c0] + part[ei][c0 + 1] + part[ei][c0 + 2] + part[ei][c0 + 3];
                if (NWE == 8 && H == 1) lg += part[ei][4] + part[ei][5] + part[ei][6] + part[ei][7];
                logit[(size_t)ipos[e] * H + h] = lg;
            }
        }
        __syncthreads();
    }
}

// ---------------- GATv2 fused reduce: softmax + aggregate + head-mean + LN + ELU ------
// warp per node; edges for node contiguous in sorted logit/psrc arrays.
template <int OUT, int H>
__global__ void __launch_bounds__(256)
k_gat_reduce(const float* __restrict__ xl, const float* __restrict__ slog,
             const int* __restrict__ rowptr, const int* __restrict__ psrc,
             const float* __restrict__ bias, const float* __restrict__ gg,
             const float* __restrict__ bb, float* __restrict__ out) {
    const int R = OUT / 32;
    __shared__ float csm[8][32 * H];
    __shared__ int   ssm2[8][32];
    int warp = threadIdx.x >> 5, lane = threadIdx.x & 31;
    int node = blockIdx.x * 8 + warp;
    if (node >= NN) return;
    int r0 = rowptr[node], r1 = rowptr[node + 1], cnt = r1 - r0;
    // max per head
    float mx[H];
    #pragma unroll
    for (int h = 0; h < H; h++) mx[h] = -FLT_MAX;
    for (int j = lane; j < cnt; j += 32) {
        #pragma unroll
        for (int h = 0; h < H; h++) mx[h] = fmaxf(mx[h], slog[(size_t)(r0 + j) * H + h]);
    }
    #pragma unroll
    for (int h = 0; h < H; h++)
        #pragma unroll
        for (int o = 16; o; o >>= 1) mx[h] = fmaxf(mx[h], __shfl_xor_sync(0xffffffffu, mx[h], o));
    // denom per head
    float den[H];
    #pragma unroll
    for (int h = 0; h < H; h++) den[h] = 0.f;
    for (int j = lane; j < cnt; j += 32) {
        #pragma unroll
        for (int h = 0; h < H; h++) den[h] += expf(slog[(size_t)(r0 + j) * H + h] - mx[h]);
    }
    float inv[H];
    #pragma unroll
    for (int h = 0; h < H; h++) {
        #pragma unroll
        for (int o = 16; o; o >>= 1) den[h] += __shfl_xor_sync(0xffffffffu, den[h], o);
        inv[h] = 1.f / fmaxf(den[h], 1e-16f);
    }
    // weighted aggregation
    float acc[R];
    #pragma unroll
    for (int j = 0; j < R; j++) acc[j] = 0.f;
    for (int j0 = 0; j0 < cnt; j0 += 32) {
        int jj = j0 + lane;
        if (jj < cnt) {
            ssm2[warp][lane] = psrc[r0 + jj];
            #pragma unroll
            for (int h = 0; h < H; h++)
                csm[warp][lane * H + h] = expf(slog[(size_t)(r0 + jj) * H + h] - mx[h]) * inv[h];
        }
        __syncwarp();
        int lim = min(32, cnt - j0);
        for (int k = 0; k < lim; k++) {
            int s = ssm2[warp][k];
            const float* row = xl + (size_t)s * OUT;
            if (H == 2) {
                float c0 = csm[warp][k * 2], c1 = csm[warp][k * 2 + 1];
                #pragma unroll
                for (int j = 0; j < R; j++)
                    acc[j] = fmaf((j < R / 2) ? c0 : c1, row[j * 32 + lane], acc[j]);
            } else {
                float c0 = csm[warp][k];
                #pragma unroll
                for (int j = 0; j < R; j++)
                    acc[j] = fmaf(c0, row[j * 32 + lane], acc[j]);
            }
        }
        __syncwarp();
    }
    // head mean + bias
    float v[4];
    #pragma unroll
    for (int j = 0; j < 4; j++) {
        if (H == 2) v[j] = 0.5f * (acc[j] + acc[j + 4]) + bias[j * 32 + lane];
        else        v[j] = acc[j] + bias[j * 32 + lane];
    }
    // LayerNorm over 128 (4 regs x 32 lanes)
    float s = v[0] + v[1] + v[2] + v[3];
    #pragma unroll
    for (int o = 16; o; o >>= 1) s += __shfl_xor_sync(0xffffffffu, s, o);
    float mu = s * (1.f / 128.f);
    float sq = 0.f;
    #pragma unroll
    for (int j = 0; j < 4; j++) { v[j] -= mu; sq = fmaf(v[j], v[j], sq); }
    #pragma unroll
    for (int o = 16; o; o >>= 1) sq += __shfl_xor_sync(0xffffffffu, sq, o);
    float is = rsqrtf(sq * (1.f / 128.f) + 1e-5f);
    #pragma unroll
    for (int j = 0; j < 4; j++) {
        int oi = j * 32 + lane;
        float o2 = v[j] * is * gg[oi] + bb[oi];
        out[(size_t)node * 128 + oi] = o2 > 0.f ? o2 : (expf(o2) - 1.f);
    }
}

// ---------------- classifier: per-edge 320->128->64->1 MLP, FFMA2, EB=6 ----------------
#define CLS_EB 6
#define CLS_SMEM_FLOATS (CIN*HID + HID*64 + 64 + 128 + 64)
__global__ void __launch_bounds__(256, 1)
k_classifier(const float* __restrict__ h2, const float* __restrict__ ea,
             const int* __restrict__ src, const int* __restrict__ dst,
             const float* __restrict__ c1w, const float* __restrict__ c1b,
             const float* __restrict__ c2w, const float* __restrict__ c2b,
             const float* __restrict__ c3w, const float* __restrict__ c3b,
             float* __restrict__ out) {
    extern __shared__ float sm[];
    float* c1s = sm;
    float* c2s = c1s + CIN * HID;
    float* c3s = c2s + HID * 64;
    float* b1s = c3s + 64;
    float* b2s = b1s + 128;
    int tid = threadIdx.x;
    for (int i = tid; i < CIN * HID; i += 256) c1s[i] = c1w[i];
    for (int i = tid; i < HID * 64; i += 256) c2s[i] = c2w[i];
    if (tid < 64)  c3s[tid] = c3w[tid];
    if (tid < 128) b1s[tid] = c1b[tid];
    if (tid < 64)  b2s[tid] = c2b[tid];
    __syncthreads();
    const ulonglong2* c1p = (const ulonglong2*)c1s;
    const ull* c2p = (const ull*)c2s;
    float c3bv = c3b[0];
    int warp = tid >> 5, lane = tid & 31;
    const int stride = gridDim.x * 8 * CLS_EB;
    for (int e0 = (blockIdx.x * 8 + warp) * CLS_EB; e0 < EE; e0 += stride) {
        float er[CLS_EB][10];
        #pragma unroll
        for (int ei = 0; ei < CLS_EB; ei++) {
            int e = e0 + ei;
            if (e < EE) {
                int s = src[e], d = dst[e];
                #pragma unroll
                for (int r = 0; r < 4; r++) er[ei][r]     = h2[(size_t)s * HID + r * 32 + lane];
                #pragma unroll
                for (int r = 0; r < 4; r++) er[ei][4 + r] = h2[(size_t)d * HID + r * 32 + lane];
                er[ei][8] = ea[(size_t)e * ED + lane];
                er[ei][9] = ea[(size_t)e * ED + 32 + lane];
            } else {
                #pragma unroll
                for (int r = 0; r < 10; r++) er[ei][r] = 0.f;
            }
        }
        ull a1p[CLS_EB][2];
        {
            float4 bb4 = ((const float4*)b1s)[lane];
            ull p0 = pk2(bb4.x, bb4.y), p1 = pk2(bb4.z, bb4.w);
            #pragma unroll
            for (int ei = 0; ei < CLS_EB; ei++) { a1p[ei][0] = p0; a1p[ei][1] = p1; }
        }
        #pragma unroll
        for (int r = 0; r < 10; r++) {
            #pragma unroll
            for (int kk = 0; kk < 32; kk++) {
                ulonglong2 w2 = c1p[(r * 32 + kk) * 32 + lane];
                #pragma unroll
                for (int ei = 0; ei < CLS_EB; ei++) {
                    ull bp = dup2(__shfl_sync(0xffffffffu, er[ei][r], kk));
                    a1p[ei][0] = ffma2(bp, w2.x, a1p[ei][0]);
                    a1p[ei][1] = ffma2(bp, w2.y, a1p[ei][1]);
                }
            }
        }
        float a1f[CLS_EB][4];
        #pragma unroll
        for (int ei = 0; ei < CLS_EB; ei++) {
            upk2(a1p[ei][0], a1f[ei][0], a1f[ei][1]);
            upk2(a1p[ei][1], a1f[ei][2], a1f[ei][3]);
            #pragma unroll
            for (int c = 0; c < 4; c++) a1f[ei][c] = fmaxf(a1f[ei][c], 0.f);
        }
        ull a2p[CLS_EB];
        {
            float2 bb2 = ((const float2*)b2s)[lane];
            ull p = pk2(bb2.x, bb2.y);
            #pragma unroll
            for (int ei = 0; ei < CLS_EB; ei++) a2p[ei] = p;
        }
        #pragma unroll
        for (int kq = 0; kq < 32; kq++) {
            #pragma unroll
            for (int c = 0; c < 4; c++) {
                ull w2 = c2p[(kq * 4 + c) * 32 + lane];
                #pragma unroll
                for (int ei = 0; ei < CLS_EB; ei++) {
                    ull bp = dup2(__shfl_sync(0xffffffffu, a1f[ei][c], kq));
                    a2p[ei] = ffma2(bp, w2, a2p[ei]);
                }
            }
        }
        float w3a = c3s[lane * 2], w3b = c3s[lane * 2 + 1];
        #pragma unroll
        for (int ei = 0; ei < CLS_EB; ei++) {
            float x, y; upk2(a2p[ei], x, y);
            float v = fmaxf(x, 0.f) * w3a + fmaxf(y, 0.f) * w3b;
            #pragma unroll
            for (int o = 16; o; o >>= 1) v += __shfl_xor_sync(0xffffffffu, v, o);
            int e = e0 + ei;
            if (lane == 0 && e < EE) out[e] = v + c3bv;
        }
    }
}

// ---------------- launch ----------------
static inline int cdiv(long a, long b) { return (int)((a + b - 1) / b); }

extern "C" void kernel_launch(void* const* d_in, const int* in_sizes, int n_in,
                              void* d_out, int out_size) {
    const float* node_stats = (const float*)d_in[1];
    const int*   ei   = (const int*)d_in[2];
    const int*   src  = ei;
    const int*   dst  = ei + EE;
    const float* ea   = (const float*)d_in[3];
    const float* epw  = (const float*)d_in[4];
    const float* epb  = (const float*)d_in[5];
    const float* g1wl = (const float*)d_in[6];
    const float* g1wr = (const float*)d_in[7];
    const float* g1we = (const float*)d_in[8];
    const float* g1att= (const float*)d_in[9];
    const float* g1b  = (const float*)d_in[10];
    const float* n1g  = (const float*)d_in[11];
    const float* n1b  = (const float*)d_in[12];
    const float* g2wl = (const float*)d_in[13];
    const float* g2wr = (const float*)d_in[14];
    const float* g2we = (const float*)d_in[15];
    const float* g2att= (const float*)d_in[16];
    const float* g2b  = (const float*)d_in[17];
    const float* n2g  = (const float*)d_in[18];
    const float* n2b  = (const float*)d_in[19];
    const float* c1w  = (const float*)d_in[20];
    const float* c1b  = (const float*)d_in[21];
    const float* c2w  = (const float*)d_in[22];
    const float* c2b  = (const float*)d_in[23];
    const float* c3w  = (const float*)d_in[24];
    const float* c3b  = (const float*)d_in[25];
    float* out = (float*)d_out;

    float *xsum_out, *xsum_in, *loop, *xi, *xl1, *xr1, *logit1, *h1;
    float *xl2, *xr2, *logit2, *h2;
    int *deg_out, *deg_in, *rowptr, *cursor, *psrc, *ipos;
    cudaGetSymbolAddress((void**)&xsum_out, g_xsum_out);
    cudaGetSymbolAddress((void**)&xsum_in,  g_xsum_in);
    cudaGetSymbolAddress((void**)&deg_out,  g_deg_out);
    cudaGetSymbolAddress((void**)&deg_in,   g_deg_in);
    cudaGetSymbolAddress((void**)&loop,     g_loop);
    cudaGetSymbolAddress((void**)&xi,       g_xi);
    cudaGetSymbolAddress((void**)&xl1,      g_xl1);
    cudaGetSymbolAddress((void**)&xr1,      g_xr1);
    cudaGetSymbolAddress((void**)&logit1,   g_logit1);
    cudaGetSymbolAddress((void**)&h1,       g_h1);
    cudaGetSymbolAddress((void**)&xl2,      g_xl2);
    cudaGetSymbolAddress((void**)&xr2,      g_xr2);
    cudaGetSymbolAddress((void**)&logit2,   g_logit2);
    cudaGetSymbolAddress((void**)&h2,       g_h2);
    cudaGetSymbolAddress((void**)&rowptr,   g_rowptr);
    cudaGetSymbolAddress((void**)&cursor,   g_cursor);
    cudaGetSymbolAddress((void**)&psrc,     g_psrc);
    cudaGetSymbolAddress((void**)&ipos,     g_ipos);

    cudaMemsetAsync(xsum_out, 0, sizeof(float) * NN * ND);
    cudaMemsetAsync(xsum_in,  0, sizeof(float) * NN * ND);
    cudaMemsetAsync(deg_out,  0, sizeof(int) * NN);
    cudaMemsetAsync(deg_in,   0, sizeof(int) * NN);
    cudaMemsetAsync(loop,     0, sizeof(float) * NN * ED);

    k_embed_scatter<<<2048, 256>>>(src, dst, ea, epw, epb, xsum_out, xsum_in,
                                   deg_out, deg_in, loop);
    k_build_xi<<<cdiv((long)NN * GIN, 256), 256>>>(node_stats, xsum_out, xsum_in, deg_out, deg_in, xi);
    k_loop_div<<<cdiv((long)NN * ED, 256), 256>>>(loop, deg_in);

    // CSR build (by dst, self-loops appended per row)
    k_prefix<<<1, 1024>>>(deg_in, rowptr, cursor);
    k_perm<<<cdiv(E2T, 256), 256>>>(src, dst, cursor, psrc, ipos);

    // GAT layer 1
    k_gemm<<<dim3(4, cdiv(NN, BM)), 256>>>(xi, g1wl, xl1, NN, GIN, 256);
    k_gemm<<<dim3(4, cdiv(NN, BM)), 256>>>(xi, g1wr, xr1, NN, GIN, 256);
    k_gat_logits<256, 2><<<2048, 256>>>(xl1, xr1, ea, loop, g1we, g1att, src, dst, ipos, logit1);
    k_gat_reduce<256, 2><<<cdiv(NN, 8), 256>>>(xl1, logit1, rowptr, psrc, g1b, n1g, n1b, h1);

    // GAT layer 2
    k_gemm<<<dim3(2, cdiv(NN, BM)), 256>>>(h1, g2wl, xl2, NN, HID, HID);
    k_gemm<<<dim3(2, cdiv(NN, BM)), 256>>>(h1, g2wr, xr2, NN, HID, HID);
    k_gat_logits<128, 1><<<2048, 256>>>(xl2, xr2, ea, loop, g2we, g2att, src, dst, ipos, logit2);
    k_gat_reduce<128, 1><<<cdiv(NN, 8), 256>>>(xl2, logit2, rowptr, psrc, g2b, n2g, n2b, h2);

    // classifier
    cudaFuncSetAttribute(k_classifier, cudaFuncAttributeMaxDynamicSharedMemorySize,
                         CLS_SMEM_FLOATS * sizeof(float));
    k_classifier<<<148, 256, CLS_SMEM_FLOATS * sizeof(float)>>>(
        h2, ea, src, dst, c1w, c1b, c2w, c2b, c3w, c3b, out);
}